// round 9
// baseline (speedup 1.0000x reference)
#include <cuda_runtime.h>
#include <cuda_fp16.h>
#include <math.h>

#define N 512
#define NIMG 128
#define NFREQ 257
#define RS 65536                 // image scratch k-stride in half2 (=128*512)

// ---------------- device scratch ------------------------------------------------------------
static __device__ __half2 g_scratch[(size_t)NFREQ * RS];  // c-major: [k][b*512+r], ~67MB, fp16
static __device__ __half2 g_hrow[(size_t)NFREQ * N];      // rowFFT of hann, [k][r], 0.5MB
static __device__ float2  g_tw[N];                        // W_512^k
static __device__ float   g_hann[N * N];                  // window table, 1MB
static __device__ float   g_parts[NIMG * 64];
static __device__ float   g_hparts[64];
static __device__ float   g_accum[N * NFREQ];             // half-plane sum |F|^2 (unshifted)
static __device__ float   g_psum[32][NFREQ];
static __device__ float   g_pcnt[32][NFREQ];

__device__ __forceinline__ int adr2(int i) { return i + (i >> 3); }

// ---- packed f32x2 helpers -------------------------------------------------------------------
union F2U { float2 f; unsigned long long u; };
__device__ __forceinline__ float2 padd(float2 a, float2 b) {
    F2U A, B, C; A.f = a; B.f = b;
    asm("add.rn.f32x2 %0, %1, %2;" : "=l"(C.u) : "l"(A.u), "l"(B.u));
    return C.f;
}
__device__ __forceinline__ float2 psub(float2 a, float2 b) {
    F2U A, B, C; A.f = a; B.f = b;
    asm("fma.rn.f32x2 %0, %1, %2, %3;"
        : "=l"(C.u) : "l"(B.u), "l"(0xBF800000BF800000ULL), "l"(A.u));
    return C.f;
}
__device__ __forceinline__ float2 cmulf2(float2 a, float2 w) {
    return make_float2(a.x * w.x - a.y * w.y, a.x * w.y + a.y * w.x);
}

// ---- natural-order 8-point DFT --------------------------------------------------------------
__device__ __forceinline__ void dft8(float2* t) {
    float2 b0 = t[0], b1 = t[4], b2 = t[2], b3 = t[6];
    float2 b4 = t[1], b5 = t[5], b6 = t[3], b7 = t[7];
    float2 u0 = padd(b0, b1), u1 = psub(b0, b1), u2 = padd(b2, b3), u3 = psub(b2, b3);
    float2 u4 = padd(b4, b5), u5 = psub(b4, b5), u6 = padd(b6, b7), u7 = psub(b6, b7);
    float2 v0 = padd(u0, u2), v2 = psub(u0, u2);
    float2 v1 = make_float2(u1.x + u3.y, u1.y - u3.x);
    float2 v3 = make_float2(u1.x - u3.y, u1.y + u3.x);
    float2 v4 = padd(u4, u6), v6 = psub(u4, u6);
    float2 v5 = make_float2(u5.x + u7.y, u5.y - u7.x);
    float2 v7 = make_float2(u5.x - u7.y, u5.y + u7.x);
    const float C = 0.70710678118654752f;
    float2 a5 = make_float2(C * (v5.x + v5.y), C * (v5.y - v5.x));
    float2 a7 = make_float2(C * (v7.y - v7.x), -C * (v7.x + v7.y));
    t[0] = padd(v0, v4); t[4] = psub(v0, v4);
    t[1] = padd(v1, a5); t[5] = psub(v1, a5);
    t[2] = make_float2(v2.x + v6.y, v2.y - v6.x);
    t[6] = make_float2(v2.x - v6.y, v2.y + v6.x);
    t[3] = padd(v3, a7); t[7] = psub(v3, a7);
}

// ---- 8x8 float2 transpose across 8 lanes (XOR network, 3 rounds) ----------------------------
__device__ __forceinline__ void transpose8(float2* u, int jj) {
#pragma unroll
    for (int k = 0; k < 3; k++) {
        const int m = 1 << k;
        bool hi = (jj & m) != 0;
#pragma unroll
        for (int i0 = 0; i0 < 8; i0++) {
            if ((i0 & m) == 0) {
                int i1 = i0 | m;
                F2U snd; snd.f = hi ? u[i0] : u[i1];
                F2U rcv; rcv.u = __shfl_xor_sync(0xffffffffu, snd.u, m);
                if (hi) u[i0] = rcv.f; else u[i1] = rcv.f;
            }
        }
    }
}

// ---------------- kernel 0: init (twiddles, hann table, zero accumulators) -------------------
__global__ void k_init() {
    int p = blockIdx.x * blockDim.x + threadIdx.x;
    {
        int i = p >> 9, j = p & 511;
        const float STEP = 512.0f / 511.0f;
        float lc = fmaf((float)j, STEP, -256.0f);
        float lr = fmaf((float)i, STEP, -256.0f);
        float rd = sqrtf(lc * lc + lr * lr);
        g_hann[p] = (rd > 256.0f) ? 0.0f : 0.5f * (1.0f + cospif(rd * (1.0f / 256.0f)));
    }
    if (p < N * NFREQ) g_accum[p] = 0.f;
    if (p < N) {
        double ang = -6.283185307179586476925286766559 * (double)p / 512.0;
        g_tw[p] = make_float2((float)cos(ang), (float)sin(ang));
    }
    if (p < 32 * NFREQ) { ((float*)g_psum)[p] = 0.f; ((float*)g_pcnt)[p] = 0.f; }
}

// ---------------- kernel 1: DIF row FFTs, 2 real rows packed per FFT -------------------------
// 4 FFTs per 256-thread block; one thread per (pair,k) in the unpack writes BOTH rows.
__global__ void __launch_bounds__(256) k_rowfft(const float* __restrict__ src,
                                                __half2* __restrict__ dst,
                                                float* __restrict__ parts,
                                                int kstride) {
    __shared__ float2 smA[4][576];     // stage-0 output
    __shared__ float2 smB[4][576];     // final spectrum, natural frequency index
    __shared__ float red[8];
    int b   = blockIdx.x >> 6;
    int r0  = (blockIdx.x & 63) << 3;
    int tid = threadIdx.x;
    int f   = tid >> 6, tau = tid & 63;
    int g   = tau >> 3, jj = tau & 7;
    int rowA = r0 + 2 * f;
    size_t srcbase = ((size_t)b << 18) + ((size_t)rowA << 9);
    const float* hA = g_hann + (rowA << 9);
    float2* sA = smA[f];
    float2* sB = smB[f];

    // ---- load + stage 0 (stride 64) in registers ----
    float2 t[8];
    float lsum = 0.f;
#pragma unroll
    for (int m = 0; m < 8; m++) {
        int c = tau + (m << 6);
        float va = src ? src[srcbase + c]       : 1.0f;
        float vb = src ? src[srcbase + 512 + c] : 1.0f;
        lsum += va + vb;
        t[m] = make_float2(va * hA[c], vb * hA[512 + c]);
    }
    dft8(t);
    int pbS = tau + (tau >> 3);
#pragma unroll
    for (int q = 1; q < 8; q++) t[q] = cmulf2(t[q], g_tw[tau * q]);
#pragma unroll
    for (int q = 0; q < 8; q++) sA[pbS + 72 * q] = t[q];

    // per-warp pixel sums (consumed after the final block barrier)
#pragma unroll
    for (int o = 16; o; o >>= 1) lsum += __shfl_down_sync(0xffffffffu, lsum, o);
    if ((tid & 31) == 0) red[tid >> 5] = lsum;
    __syncthreads();

    // ---- stage 1 (stride 8) in registers ----
    float2 u[8];
    int pbL = 72 * g + jj;
#pragma unroll
    for (int m = 0; m < 8; m++) u[m] = sA[pbL + 9 * m];
    dft8(u);
    int e1 = jj << 3;
#pragma unroll
    for (int q = 1; q < 8; q++) u[q] = cmulf2(u[q], g_tw[e1 * q]);

    // ---- exchange via shuffle + stage 2 in registers ----
    transpose8(u, jj);
    dft8(u);

    // store at natural frequency index
#pragma unroll
    for (int m = 0; m < 8; m++)
        sB[adr2((m << 6) + (jj << 3) + g)] = u[m];
    __syncthreads();

    if (tid == 0) {
        float tot = 0.f;
#pragma unroll
        for (int p = 0; p < 8; p++) tot += red[p];
        parts[blockIdx.x] = tot;
    }

    // ---- Hermitian unpack: one thread per (pair,k) writes both rows as one STG.64 ----
    int p      = tid & 3;          // FFT pair index
    int kslot  = tid >> 2;         // 0..63
    float2* so = smB[p];
    size_t dbase = ((size_t)b << 9) + r0 + 2 * p;
#pragma unroll
    for (int it = 0; it < 5; it++) {
        int k = kslot + (it << 6);
        if (k < NFREQ) {
            float2 z = so[adr2(k)];
            float2 y = so[adr2((512 - k) & 511)];
            __half2 A = __floats2half2_rn(0.5f * (z.x + y.x), 0.5f * (z.y - y.y));
            __half2 B = __floats2half2_rn(0.5f * (z.y + y.y), 0.5f * (y.x - z.x));
            F2U pack; ((__half2*)&pack.u)[0] = A; ((__half2*)&pack.u)[1] = B;
            *reinterpret_cast<unsigned long long*>(
                &dst[(size_t)k * kstride + dbase]) = pack.u;
        }
    }
}

// ---------------- kernel 2: DIF column FFTs — 4 cols x 16 images, 1 syncthreads/image --------
__global__ void __launch_bounds__(256, 4) k_colfft() {
    __shared__ float2 smbuf[2][4][576];    // double-buffered stage-0 output
    __shared__ float smean[16];
    int ct  = blockIdx.x % 65;
    int grp = blockIdx.x / 65;             // 0..7 : 16 images each
    int f   = threadIdx.x >> 6;
    int tau = threadIdx.x & 63;
    int g   = tau >> 3, jj = tau & 7;
    int c   = (ct << 2) + f;
    bool valid = (c < NFREQ);
    size_t cbase = valid ? (size_t)c * RS : 0;
    int b0 = grp << 4;

    // ---- cached correction vector (invariant over image loop), fp32 in regs ----
    float2 hv[8];
    size_t hbase = valid ? ((size_t)c << 9) : 0;
#pragma unroll
    for (int m = 0; m < 8; m++)
        hv[m] = valid ? __half22float2(g_hrow[hbase + tau + (m << 6)])
                      : make_float2(0.f, 0.f);

    // ---- prefetch image 0 (raw fp16, converted at use) ----
    __half2 traw[8];
#pragma unroll
    for (int m = 0; m < 8; m++)
        traw[m] = valid ? g_scratch[cbase + ((size_t)b0 << 9) + tau + (m << 6)]
                        : __half2(__float2half2_rn(0.f));

    // ---- fused per-image means: warp w reduces images b0+2w, b0+2w+1 ----
    {
        int w = threadIdx.x >> 5, l = threadIdx.x & 31;
        float v1 = g_parts[((b0 + 2 * w)     << 6) + l] + g_parts[((b0 + 2 * w)     << 6) + 32 + l];
        float v2 = g_parts[((b0 + 2 * w + 1) << 6) + l] + g_parts[((b0 + 2 * w + 1) << 6) + 32 + l];
#pragma unroll
        for (int o = 16; o; o >>= 1) {
            v1 += __shfl_down_sync(0xffffffffu, v1, o);
            v2 += __shfl_down_sync(0xffffffffu, v2, o);
        }
        if (l == 0) {
            smean[2 * w]     = v1 * (1.0f / 262144.0f);
            smean[2 * w + 1] = v2 * (1.0f / 262144.0f);
        }
        __syncthreads();
    }

    int pbS = tau + (tau >> 3);
    int pbL = 72 * g + jj;
    int e1 = jj << 3;

    float acc[8];
#pragma unroll
    for (int m = 0; m < 8; m++) acc[m] = 0.f;

    for (int bi = 0; bi < 16; bi++) {
        float mean = smean[bi];
        float2* s = smbuf[bi & 1][f];

        // stage 0 (registers): convert + mean correction + dft8 + twiddle
        float2 tc[8];
#pragma unroll
        for (int m = 0; m < 8; m++) {
            float2 v = __half22float2(traw[m]);
            tc[m] = make_float2(fmaf(-mean, hv[m].x, v.x),
                                fmaf(-mean, hv[m].y, v.y));
        }
        dft8(tc);
#pragma unroll
        for (int q = 1; q < 8; q++) tc[q] = cmulf2(tc[q], g_tw[tau * q]);
#pragma unroll
        for (int q = 0; q < 8; q++) s[pbS + 72 * q] = tc[q];

        // prefetch next image into dead traw — hidden across barrier + stages 1-2
        if (bi < 15 && valid) {
            int b = b0 + bi + 1;
#pragma unroll
            for (int m = 0; m < 8; m++)
                traw[m] = g_scratch[cbase + ((size_t)b << 9) + tau + (m << 6)];
        }
        __syncthreads();   // data-ready; WAR vs image bi-2 guaranteed by double buffer

        // stage 1 in registers
        float2 u[8];
#pragma unroll
        for (int m = 0; m < 8; m++) u[m] = s[pbL + 9 * m];
        dft8(u);
#pragma unroll
        for (int q = 1; q < 8; q++) u[q] = cmulf2(u[q], g_tw[e1 * q]);

        // shuffle exchange + stage 2 + accumulate
        transpose8(u, jj);
        dft8(u);
#pragma unroll
        for (int m = 0; m < 8; m++)
            acc[m] = fmaf(u[m].x, u[m].x, fmaf(u[m].y, u[m].y, acc[m]));
    }

    if (valid) {
        int rlo = (jj << 3) + g;
#pragma unroll
        for (int m = 0; m < 8; m++) {
            int r = (m << 6) + rlo;            // natural frequency index
            atomicAdd(&g_accum[r * NFREQ + c], acc[m]);
        }
    }
}

// ---------------- kernel 3: nps2D + two-level radial binning ---------------------------------
__global__ void __launch_bounds__(256) k_finalize2d(float* __restrict__ out) {
    __shared__ float ssum[NFREQ];
    __shared__ float scnt[NFREQ];
    int i = blockIdx.x;
    int tid = threadIdx.x;
    if (tid < NFREQ) { ssum[tid] = 0.f; scnt[tid] = 0.f; }
    if (tid + 256 < NFREQ) { ssum[tid + 256] = 0.f; scnt[tid + 256] = 0.f; }
    __syncthreads();

    const float SC = (float)(0.01 / (262144.0 * 128.0));
    int xi = i - 256;
#pragma unroll
    for (int h = 0; h < 2; h++) {
        int j = tid + (h << 8);
        int u = i ^ 256, v = j ^ 256;
        if (v > 256) { u = (512 - u) & 511; v = 512 - v; }
        float val = g_accum[u * NFREQ + v] * SC;
        out[NFREQ + (i << 9) + j] = val;
        int yj = j - 256;
        int rad = __float2int_rn(__fsqrt_rn((float)(xi * xi + yj * yj)));
        if (rad < NFREQ) {
            atomicAdd(&ssum[rad], val);
            atomicAdd(&scnt[rad], 1.0f);
        }
    }
    __syncthreads();

    int part = i & 31;
    if (tid < NFREQ && (ssum[tid] != 0.f || scnt[tid] != 0.f)) {
        atomicAdd(&g_psum[part][tid], ssum[tid]);
        atomicAdd(&g_pcnt[part][tid], scnt[tid]);
    }
    if (tid + 256 < NFREQ && (ssum[tid + 256] != 0.f || scnt[tid + 256] != 0.f)) {
        atomicAdd(&g_psum[part][tid + 256], ssum[tid + 256]);
        atomicAdd(&g_pcnt[part][tid + 256], scnt[tid + 256]);
    }
}

// ---------------- kernel 4: nps1D and f1D ----------------------------------------------------
__global__ void k_finalize1d(float* __restrict__ out) {
    int k = threadIdx.x;
    if (k < NFREQ) {
        float s = 0.f, c = 0.f;
#pragma unroll
        for (int p = 0; p < 32; p++) { s += g_psum[p][k]; c += g_pcnt[p][k]; }
        out[k] = s / c;
        out[NFREQ + N * N + k] = 5.0f * (float)k / 256.0f;
    }
}

extern "C" void kernel_launch(void* const* d_in, const int* in_sizes, int n_in,
                              void* d_out, int out_size) {
    const float* x = (const float*)d_in[0];
    float* out = (float*)d_out;

    float* pparts;   cudaGetSymbolAddress((void**)&pparts,   g_parts);
    float* phparts;  cudaGetSymbolAddress((void**)&phparts,  g_hparts);
    __half2* pscr;   cudaGetSymbolAddress((void**)&pscr,     g_scratch);
    __half2* phrow;  cudaGetSymbolAddress((void**)&phrow,    g_hrow);

    k_init<<<1024, 256>>>();
    k_rowfft<<<NIMG * 64, 256>>>(x, pscr, pparts, RS);          // images: FFT(v*h)
    k_rowfft<<<64, 256>>>(nullptr, phrow, phparts, N);          // window: FFT(h)
    k_colfft<<<65 * 8, 256>>>();                                // 4 cols x 16 images per block
    k_finalize2d<<<N, 256>>>(out);
    k_finalize1d<<<1, NFREQ>>>(out);
}

// round 10
// speedup vs baseline: 1.1817x; 1.1817x over previous
#include <cuda_runtime.h>
#include <cuda_fp16.h>
#include <math.h>

#define N 512
#define NIMG 128
#define NFREQ 257
#define RS 65536                 // image scratch k-stride in half2 (=128*512)

#define BARSYNC(id) asm volatile("bar.sync %0, 64;" :: "r"(id) : "memory")

// ---------------- device scratch ------------------------------------------------------------
static __device__ __half2 g_scratch[(size_t)NFREQ * RS];  // c-major: [k][b*512+r], ~67MB, fp16
static __device__ __half2 g_hrow[(size_t)NFREQ * N];      // rowFFT of hann, [k][r], 0.5MB
static __device__ float2  g_tw[N];                        // W_512^k
static __device__ float   g_hann[N * N];                  // window table, 1MB
static __device__ float   g_parts[NIMG * 64];
static __device__ float   g_hparts[64];
static __device__ float   g_accum[N * NFREQ];             // half-plane sum |F|^2 (unshifted)
static __device__ float   g_psum[32][NFREQ];
static __device__ float   g_pcnt[32][NFREQ];

__device__ __forceinline__ int adr2(int i) { return i + (i >> 3); }

// ---- packed f32x2 helpers -------------------------------------------------------------------
union F2U { float2 f; unsigned long long u; };
__device__ __forceinline__ float2 padd(float2 a, float2 b) {
    F2U A, B, C; A.f = a; B.f = b;
    asm("add.rn.f32x2 %0, %1, %2;" : "=l"(C.u) : "l"(A.u), "l"(B.u));
    return C.f;
}
__device__ __forceinline__ float2 psub(float2 a, float2 b) {
    F2U A, B, C; A.f = a; B.f = b;
    asm("fma.rn.f32x2 %0, %1, %2, %3;"
        : "=l"(C.u) : "l"(B.u), "l"(0xBF800000BF800000ULL), "l"(A.u));
    return C.f;
}
__device__ __forceinline__ float2 cmulf2(float2 a, float2 w) {
    return make_float2(a.x * w.x - a.y * w.y, a.x * w.y + a.y * w.x);
}

// ---- natural-order 8-point DFT --------------------------------------------------------------
__device__ __forceinline__ void dft8(float2* t) {
    float2 b0 = t[0], b1 = t[4], b2 = t[2], b3 = t[6];
    float2 b4 = t[1], b5 = t[5], b6 = t[3], b7 = t[7];
    float2 u0 = padd(b0, b1), u1 = psub(b0, b1), u2 = padd(b2, b3), u3 = psub(b2, b3);
    float2 u4 = padd(b4, b5), u5 = psub(b4, b5), u6 = padd(b6, b7), u7 = psub(b6, b7);
    float2 v0 = padd(u0, u2), v2 = psub(u0, u2);
    float2 v1 = make_float2(u1.x + u3.y, u1.y - u3.x);
    float2 v3 = make_float2(u1.x - u3.y, u1.y + u3.x);
    float2 v4 = padd(u4, u6), v6 = psub(u4, u6);
    float2 v5 = make_float2(u5.x + u7.y, u5.y - u7.x);
    float2 v7 = make_float2(u5.x - u7.y, u5.y + u7.x);
    const float C = 0.70710678118654752f;
    float2 a5 = make_float2(C * (v5.x + v5.y), C * (v5.y - v5.x));
    float2 a7 = make_float2(C * (v7.y - v7.x), -C * (v7.x + v7.y));
    t[0] = padd(v0, v4); t[4] = psub(v0, v4);
    t[1] = padd(v1, a5); t[5] = psub(v1, a5);
    t[2] = make_float2(v2.x + v6.y, v2.y - v6.x);
    t[6] = make_float2(v2.x - v6.y, v2.y + v6.x);
    t[3] = padd(v3, a7); t[7] = psub(v3, a7);
}

// ---- 8x8 float2 transpose across 8 lanes (XOR network, 3 rounds) ----------------------------
__device__ __forceinline__ void transpose8(float2* u, int jj) {
#pragma unroll
    for (int k = 0; k < 3; k++) {
        const int m = 1 << k;
        bool hi = (jj & m) != 0;
#pragma unroll
        for (int i0 = 0; i0 < 8; i0++) {
            if ((i0 & m) == 0) {
                int i1 = i0 | m;
                F2U snd; snd.f = hi ? u[i0] : u[i1];
                F2U rcv; rcv.u = __shfl_xor_sync(0xffffffffu, snd.u, m);
                if (hi) u[i0] = rcv.f; else u[i1] = rcv.f;
            }
        }
    }
}

// ---------------- kernel 0: init (twiddles, hann table, zero accumulators) -------------------
__global__ void k_init() {
    int p = blockIdx.x * blockDim.x + threadIdx.x;
    {
        int i = p >> 9, j = p & 511;
        const float STEP = 512.0f / 511.0f;
        float lc = fmaf((float)j, STEP, -256.0f);
        float lr = fmaf((float)i, STEP, -256.0f);
        float rd = sqrtf(lc * lc + lr * lr);
        g_hann[p] = (rd > 256.0f) ? 0.0f : 0.5f * (1.0f + cospif(rd * (1.0f / 256.0f)));
    }
    if (p < N * NFREQ) g_accum[p] = 0.f;
    if (p < N) {
        double ang = -6.283185307179586476925286766559 * (double)p / 512.0;
        g_tw[p] = make_float2((float)cos(ang), (float)sin(ang));
    }
    if (p < 32 * NFREQ) { ((float*)g_psum)[p] = 0.f; ((float*)g_pcnt)[p] = 0.f; }
}

// ---------------- kernel 1: DIF row FFTs, 2 real rows packed per FFT -------------------------
// 4 FFTs per 256-thread block; fp16 final-spectrum SMEM; paired unpack writes both rows.
__global__ void __launch_bounds__(256) k_rowfft(const float* __restrict__ src,
                                                __half2* __restrict__ dst,
                                                float* __restrict__ parts,
                                                int kstride) {
    __shared__ float2  smA[4][576];    // stage-0 output (fp32)
    __shared__ __half2 smB[4][576];    // final spectrum, natural freq index (fp16)
    __shared__ float red[8];
    int b   = blockIdx.x >> 6;
    int r0  = (blockIdx.x & 63) << 3;
    int tid = threadIdx.x;
    int f   = tid >> 6, tau = tid & 63;
    int g   = tau >> 3, jj = tau & 7;
    int rowA = r0 + 2 * f;
    size_t srcbase = ((size_t)b << 18) + ((size_t)rowA << 9);
    const float* hA = g_hann + (rowA << 9);
    float2*  sA = smA[f];
    __half2* sB = smB[f];

    // ---- load + stage 0 (stride 64) in registers ----
    float2 t[8];
    float lsum = 0.f;
#pragma unroll
    for (int m = 0; m < 8; m++) {
        int c = tau + (m << 6);
        float va = src ? src[srcbase + c]       : 1.0f;
        float vb = src ? src[srcbase + 512 + c] : 1.0f;
        lsum += va + vb;
        t[m] = make_float2(va * hA[c], vb * hA[512 + c]);
    }
    dft8(t);
    int pbS = tau + (tau >> 3);
#pragma unroll
    for (int q = 1; q < 8; q++) t[q] = cmulf2(t[q], g_tw[tau * q]);
#pragma unroll
    for (int q = 0; q < 8; q++) sA[pbS + 72 * q] = t[q];

    // per-warp pixel sums (consumed after the final block barrier)
#pragma unroll
    for (int o = 16; o; o >>= 1) lsum += __shfl_down_sync(0xffffffffu, lsum, o);
    if ((tid & 31) == 0) red[tid >> 5] = lsum;
    __syncthreads();

    // ---- stage 1 (stride 8) in registers ----
    float2 u[8];
    int pbL = 72 * g + jj;
#pragma unroll
    for (int m = 0; m < 8; m++) u[m] = sA[pbL + 9 * m];
    dft8(u);
    int e1 = jj << 3;
#pragma unroll
    for (int q = 1; q < 8; q++) u[q] = cmulf2(u[q], g_tw[e1 * q]);

    // ---- exchange via shuffle + stage 2 in registers ----
    transpose8(u, jj);
    dft8(u);

    // store at natural frequency index, quantized to fp16 (same quantization as dst)
#pragma unroll
    for (int m = 0; m < 8; m++)
        sB[adr2((m << 6) + (jj << 3) + g)] = __floats2half2_rn(u[m].x, u[m].y);
    __syncthreads();

    if (tid == 0) {
        float tot = 0.f;
#pragma unroll
        for (int p = 0; p < 8; p++) tot += red[p];
        parts[blockIdx.x] = tot;
    }

    // ---- Hermitian unpack: one thread per (pair,k) writes both rows as one STG.64 ----
    int p      = tid & 3;          // FFT pair index
    int kslot  = tid >> 2;         // 0..63
    __half2* so = smB[p];
    size_t dbase = ((size_t)b << 9) + r0 + 2 * p;
#pragma unroll
    for (int it = 0; it < 5; it++) {
        int k = kslot + (it << 6);
        if (k < NFREQ) {
            float2 z = __half22float2(so[adr2(k)]);
            float2 y = __half22float2(so[adr2((512 - k) & 511)]);
            __half2 A = __floats2half2_rn(0.5f * (z.x + y.x), 0.5f * (z.y - y.y));
            __half2 B = __floats2half2_rn(0.5f * (z.y + y.y), 0.5f * (y.x - z.x));
            F2U pack; ((__half2*)&pack.u)[0] = A; ((__half2*)&pack.u)[1] = B;
            *reinterpret_cast<unsigned long long*>(
                &dst[(size_t)k * kstride + dbase]) = pack.u;
        }
    }
}

// ---------------- kernel 2: DIF column FFTs — R8 structure (4 cols x 8 images), fp16 SMEM ----
__global__ void __launch_bounds__(256, 4) k_colfft() {
    __shared__ __half2 smbuf[2][4][576];   // double-buffered stage-0 output, fp16
    __shared__ float smean[8];
    int ct  = blockIdx.x % 65;
    int grp = blockIdx.x / 65;             // 0..15 : 8 images each
    int f   = threadIdx.x >> 6;
    int tau = threadIdx.x & 63;
    int g   = tau >> 3, jj = tau & 7;
    int c   = (ct << 2) + f;
    bool valid = (c < NFREQ);
    size_t cbase = valid ? (size_t)c * RS : 0;
    int b0 = grp << 3;
    int bar = f + 1;

    // ---- cached correction vector (invariant over image loop), fp32 in regs ----
    float2 hv[8];
    size_t hbase = valid ? ((size_t)c << 9) : 0;
#pragma unroll
    for (int m = 0; m < 8; m++)
        hv[m] = valid ? __half22float2(g_hrow[hbase + tau + (m << 6)])
                      : make_float2(0.f, 0.f);

    // ---- prefetch image 0 (raw fp16, converted at use) ----
    __half2 traw[8];
#pragma unroll
    for (int m = 0; m < 8; m++)
        traw[m] = valid ? g_scratch[cbase + ((size_t)b0 << 9) + tau + (m << 6)]
                        : __half2(__float2half2_rn(0.f));

    // ---- fused per-image means: warp w reduces image b0+w ----
    {
        int w = threadIdx.x >> 5, l = threadIdx.x & 31;
        float v = g_parts[((b0 + w) << 6) + l] + g_parts[((b0 + w) << 6) + 32 + l];
#pragma unroll
        for (int o = 16; o; o >>= 1) v += __shfl_down_sync(0xffffffffu, v, o);
        if (l == 0) smean[w] = v * (1.0f / 262144.0f);
        __syncthreads();
    }

    int pbS = tau + (tau >> 3);
    int pbL = 72 * g + jj;
    int e1 = jj << 3;

    float acc[8];
#pragma unroll
    for (int m = 0; m < 8; m++) acc[m] = 0.f;

    for (int bi = 0; bi < 8; bi++) {
        float mean = smean[bi];
        __half2* s = smbuf[bi & 1][f];

        // stage 0 (registers): convert + mean correction + dft8 + twiddle
        float2 tc[8];
#pragma unroll
        for (int m = 0; m < 8; m++) {
            float2 v = __half22float2(traw[m]);
            tc[m] = make_float2(fmaf(-mean, hv[m].x, v.x),
                                fmaf(-mean, hv[m].y, v.y));
        }
        dft8(tc);
#pragma unroll
        for (int q = 1; q < 8; q++) tc[q] = cmulf2(tc[q], g_tw[tau * q]);
#pragma unroll
        for (int q = 0; q < 8; q++)
            s[pbS + 72 * q] = __floats2half2_rn(tc[q].x, tc[q].y);

        // prefetch next image into dead traw — hidden across barrier + stages 1-2
        if (bi < 7 && valid) {
            int b = b0 + bi + 1;
#pragma unroll
            for (int m = 0; m < 8; m++)
                traw[m] = g_scratch[cbase + ((size_t)b << 9) + tau + (m << 6)];
        }
        BARSYNC(bar);     // data-ready; WAR vs image bi-2 guaranteed by double buffer

        // stage 1 in registers
        float2 u[8];
#pragma unroll
        for (int m = 0; m < 8; m++) u[m] = __half22float2(s[pbL + 9 * m]);
        dft8(u);
#pragma unroll
        for (int q = 1; q < 8; q++) u[q] = cmulf2(u[q], g_tw[e1 * q]);

        // shuffle exchange + stage 2 + accumulate
        transpose8(u, jj);
        dft8(u);
#pragma unroll
        for (int m = 0; m < 8; m++)
            acc[m] = fmaf(u[m].x, u[m].x, fmaf(u[m].y, u[m].y, acc[m]));
    }

    if (valid) {
        int rlo = (jj << 3) + g;
#pragma unroll
        for (int m = 0; m < 8; m++) {
            int r = (m << 6) + rlo;            // natural frequency index
            atomicAdd(&g_accum[r * NFREQ + c], acc[m]);
        }
    }
}

// ---------------- kernel 3: nps2D + two-level radial binning ---------------------------------
__global__ void __launch_bounds__(256) k_finalize2d(float* __restrict__ out) {
    __shared__ float ssum[NFREQ];
    __shared__ float scnt[NFREQ];
    int i = blockIdx.x;
    int tid = threadIdx.x;
    if (tid < NFREQ) { ssum[tid] = 0.f; scnt[tid] = 0.f; }
    if (tid + 256 < NFREQ) { ssum[tid + 256] = 0.f; scnt[tid + 256] = 0.f; }
    __syncthreads();

    const float SC = (float)(0.01 / (262144.0 * 128.0));
    int xi = i - 256;
#pragma unroll
    for (int h = 0; h < 2; h++) {
        int j = tid + (h << 8);
        int u = i ^ 256, v = j ^ 256;
        if (v > 256) { u = (512 - u) & 511; v = 512 - v; }
        float val = g_accum[u * NFREQ + v] * SC;
        out[NFREQ + (i << 9) + j] = val;
        int yj = j - 256;
        int rad = __float2int_rn(__fsqrt_rn((float)(xi * xi + yj * yj)));
        if (rad < NFREQ) {
            atomicAdd(&ssum[rad], val);
            atomicAdd(&scnt[rad], 1.0f);
        }
    }
    __syncthreads();

    int part = i & 31;
    if (tid < NFREQ && (ssum[tid] != 0.f || scnt[tid] != 0.f)) {
        atomicAdd(&g_psum[part][tid], ssum[tid]);
        atomicAdd(&g_pcnt[part][tid], scnt[tid]);
    }
    if (tid + 256 < NFREQ && (ssum[tid + 256] != 0.f || scnt[tid + 256] != 0.f)) {
        atomicAdd(&g_psum[part][tid + 256], ssum[tid + 256]);
        atomicAdd(&g_pcnt[part][tid + 256], scnt[tid + 256]);
    }
}

// ---------------- kernel 4: nps1D and f1D ----------------------------------------------------
__global__ void k_finalize1d(float* __restrict__ out) {
    int k = threadIdx.x;
    if (k < NFREQ) {
        float s = 0.f, c = 0.f;
#pragma unroll
        for (int p = 0; p < 32; p++) { s += g_psum[p][k]; c += g_pcnt[p][k]; }
        out[k] = s / c;
        out[NFREQ + N * N + k] = 5.0f * (float)k / 256.0f;
    }
}

extern "C" void kernel_launch(void* const* d_in, const int* in_sizes, int n_in,
                              void* d_out, int out_size) {
    const float* x = (const float*)d_in[0];
    float* out = (float*)d_out;

    float* pparts;   cudaGetSymbolAddress((void**)&pparts,   g_parts);
    float* phparts;  cudaGetSymbolAddress((void**)&phparts,  g_hparts);
    __half2* pscr;   cudaGetSymbolAddress((void**)&pscr,     g_scratch);
    __half2* phrow;  cudaGetSymbolAddress((void**)&phrow,    g_hrow);

    k_init<<<1024, 256>>>();
    k_rowfft<<<NIMG * 64, 256>>>(x, pscr, pparts, RS);          // images: FFT(v*h)
    k_rowfft<<<64, 256>>>(nullptr, phrow, phparts, N);          // window: FFT(h)
    k_colfft<<<65 * 16, 256>>>();                               // 4 cols x 8 images per block
    k_finalize2d<<<N, 256>>>(out);
    k_finalize1d<<<1, NFREQ>>>(out);
}

// round 11
// speedup vs baseline: 1.3269x; 1.1229x over previous
#include <cuda_runtime.h>
#include <cuda_fp16.h>
#include <math.h>

#define N 512
#define NIMG 128
#define NFREQ 257
#define RS 65536                 // image scratch k-stride in half2 (=128*512)

#define BARSYNC(id) asm volatile("bar.sync %0, 64;" :: "r"(id) : "memory")

// ---------------- device scratch ------------------------------------------------------------
static __device__ __half2 g_scratch[(size_t)NFREQ * RS];  // c-major: [k][b*512+r], ~67MB, fp16
static __device__ __half2 g_hrow[(size_t)NFREQ * N];      // rowFFT of hann, [k][r], 0.5MB
static __device__ float2  g_tw[N];                        // W_512^k
static __device__ __half2 g_hann2[256 * 512];             // hann pairs (row r, r+1), 0.5MB
static __device__ float   g_parts[NIMG * 64];
static __device__ float   g_hparts[64];
static __device__ float   g_accum[N * NFREQ];             // half-plane sum |F|^2 (unshifted)
static __device__ float   g_psum[32][NFREQ];
static __device__ float   g_pcnt[32][NFREQ];

__device__ __forceinline__ int adr2(int i) { return i + (i >> 3); }

// ---- packed helpers ---------------------------------------------------------------------
union F2U { float2 f; unsigned long long u; };
union HU  { __half2 h; unsigned int u; };
__device__ __forceinline__ float2 padd(float2 a, float2 b) {
    F2U A, B, C; A.f = a; B.f = b;
    asm("add.rn.f32x2 %0, %1, %2;" : "=l"(C.u) : "l"(A.u), "l"(B.u));
    return C.f;
}
__device__ __forceinline__ float2 psub(float2 a, float2 b) {
    F2U A, B, C; A.f = a; B.f = b;
    asm("fma.rn.f32x2 %0, %1, %2, %3;"
        : "=l"(C.u) : "l"(B.u), "l"(0xBF800000BF800000ULL), "l"(A.u));
    return C.f;
}
__device__ __forceinline__ float2 cmulf2(float2 a, float2 w) {
    return make_float2(a.x * w.x - a.y * w.y, a.x * w.y + a.y * w.x);
}

// ---- natural-order 8-point DFT --------------------------------------------------------------
__device__ __forceinline__ void dft8(float2* t) {
    float2 b0 = t[0], b1 = t[4], b2 = t[2], b3 = t[6];
    float2 b4 = t[1], b5 = t[5], b6 = t[3], b7 = t[7];
    float2 u0 = padd(b0, b1), u1 = psub(b0, b1), u2 = padd(b2, b3), u3 = psub(b2, b3);
    float2 u4 = padd(b4, b5), u5 = psub(b4, b5), u6 = padd(b6, b7), u7 = psub(b6, b7);
    float2 v0 = padd(u0, u2), v2 = psub(u0, u2);
    float2 v1 = make_float2(u1.x + u3.y, u1.y - u3.x);
    float2 v3 = make_float2(u1.x - u3.y, u1.y + u3.x);
    float2 v4 = padd(u4, u6), v6 = psub(u4, u6);
    float2 v5 = make_float2(u5.x + u7.y, u5.y - u7.x);
    float2 v7 = make_float2(u5.x - u7.y, u5.y + u7.x);
    const float C = 0.70710678118654752f;
    float2 a5 = make_float2(C * (v5.x + v5.y), C * (v5.y - v5.x));
    float2 a7 = make_float2(C * (v7.y - v7.x), -C * (v7.x + v7.y));
    t[0] = padd(v0, v4); t[4] = psub(v0, v4);
    t[1] = padd(v1, a5); t[5] = psub(v1, a5);
    t[2] = make_float2(v2.x + v6.y, v2.y - v6.x);
    t[6] = make_float2(v2.x - v6.y, v2.y + v6.x);
    t[3] = padd(v3, a7); t[7] = psub(v3, a7);
}

// ---- 8x8 half2 transpose across 8 lanes (SHFL.32, 3 rounds) ---------------------------------
// in/out: lane jj holds u[q]=elem jj+8q  ->  lane jj holds u[r]=elem 8jj+r
__device__ __forceinline__ void transpose8h(unsigned int* u, int jj) {
#pragma unroll
    for (int k = 0; k < 3; k++) {
        const int m = 1 << k;
        bool hi = (jj & m) != 0;
#pragma unroll
        for (int i0 = 0; i0 < 8; i0++) {
            if ((i0 & m) == 0) {
                int i1 = i0 | m;
                unsigned int snd = hi ? u[i0] : u[i1];
                unsigned int rcv = __shfl_xor_sync(0xffffffffu, snd, m);
                if (hi) u[i0] = rcv; else u[i1] = rcv;
            }
        }
    }
}

// ---------------- kernel 0: init (twiddles, hann pairs, zero accumulators) -------------------
__global__ void k_init() {
    int p = blockIdx.x * blockDim.x + threadIdx.x;   // 0..262143
    if (p < 256 * 512) {   // hann pair table: rows 2rp, 2rp+1 at column j
        int rp = p >> 9, j = p & 511;
        const float STEP = 512.0f / 511.0f;
        float lc = fmaf((float)j, STEP, -256.0f);
        float h0, h1;
        {
            float lr = fmaf((float)(2 * rp), STEP, -256.0f);
            float rd = sqrtf(lc * lc + lr * lr);
            h0 = (rd > 256.0f) ? 0.0f : 0.5f * (1.0f + cospif(rd * (1.0f / 256.0f)));
        }
        {
            float lr = fmaf((float)(2 * rp + 1), STEP, -256.0f);
            float rd = sqrtf(lc * lc + lr * lr);
            h1 = (rd > 256.0f) ? 0.0f : 0.5f * (1.0f + cospif(rd * (1.0f / 256.0f)));
        }
        g_hann2[p] = __floats2half2_rn(h0, h1);
    }
    if (p < N * NFREQ) g_accum[p] = 0.f;
    if (p < N) {
        double ang = -6.283185307179586476925286766559 * (double)p / 512.0;
        g_tw[p] = make_float2((float)cos(ang), (float)sin(ang));
    }
    if (p < 32 * NFREQ) { ((float*)g_psum)[p] = 0.f; ((float*)g_pcnt)[p] = 0.f; }
}

// ---------------- kernel 1: DIF row FFTs (images + window in one grid) ------------------------
// 4 FFTs per 256-thread block; fp16 smA/smB; fp16 shuffle transpose; paired hann loads.
__global__ void __launch_bounds__(256) k_rowfft(const float* __restrict__ src) {
    __shared__ __half2 smA[4][576];    // stage-0 output (fp16)
    __shared__ __half2 smB[4][576];    // final spectrum, natural freq index (fp16)
    __shared__ float red[8];
    bool win = blockIdx.x >= NIMG * 64;
    int bid  = win ? (int)blockIdx.x - NIMG * 64 : (int)blockIdx.x;
    int b    = win ? 0 : (bid >> 6);
    int r0   = (win ? bid : (bid & 63)) << 3;
    __half2* dst = win ? g_hrow : g_scratch;
    int kstride  = win ? N : RS;
    float* parts = win ? g_hparts : g_parts;

    int tid = threadIdx.x;
    int f   = tid >> 6, tau = tid & 63;
    int g   = tau >> 3, jj = tau & 7;
    int rowA = r0 + 2 * f;
    size_t srcbase = ((size_t)b << 18) + ((size_t)rowA << 9);
    const __half2* hP = g_hann2 + ((rowA >> 1) << 9);
    __half2* sA = smA[f];
    __half2* sB = smB[f];

    // ---- load + stage 0 (stride 64) in registers ----
    float2 t[8];
    float lsum = 0.f;
#pragma unroll
    for (int m = 0; m < 8; m++) {
        int c = tau + (m << 6);
        float2 h2 = __half22float2(hP[c]);
        float va = 1.0f, vb = 1.0f;
        if (!win) {
            va = src[srcbase + c];
            vb = src[srcbase + 512 + c];
            lsum += va + vb;
        }
        t[m] = make_float2(va * h2.x, vb * h2.y);
    }
    dft8(t);
    int pbS = tau + (tau >> 3);
#pragma unroll
    for (int q = 1; q < 8; q++) t[q] = cmulf2(t[q], g_tw[tau * q]);
#pragma unroll
    for (int q = 0; q < 8; q++) sA[pbS + 72 * q] = __floats2half2_rn(t[q].x, t[q].y);

    // per-warp pixel sums (consumed after the final block barrier)
#pragma unroll
    for (int o = 16; o; o >>= 1) lsum += __shfl_down_sync(0xffffffffu, lsum, o);
    if ((tid & 31) == 0) red[tid >> 5] = lsum;
    __syncthreads();

    // ---- stage 1 (stride 8) in registers ----
    float2 u[8];
    int pbL = 72 * g + jj;
#pragma unroll
    for (int m = 0; m < 8; m++) u[m] = __half22float2(sA[pbL + 9 * m]);
    dft8(u);
    int e1 = jj << 3;
#pragma unroll
    for (int q = 1; q < 8; q++) u[q] = cmulf2(u[q], g_tw[e1 * q]);

    // ---- fp16 shuffle exchange + stage 2 ----
    unsigned int uh[8];
#pragma unroll
    for (int q = 0; q < 8; q++) { HU h; h.h = __floats2half2_rn(u[q].x, u[q].y); uh[q] = h.u; }
    transpose8h(uh, jj);
#pragma unroll
    for (int m = 0; m < 8; m++) { HU h; h.u = uh[m]; u[m] = __half22float2(h.h); }
    dft8(u);

    // store at natural frequency index (fp16)
#pragma unroll
    for (int m = 0; m < 8; m++)
        sB[adr2((m << 6) + (jj << 3) + g)] = __floats2half2_rn(u[m].x, u[m].y);
    __syncthreads();

    if (tid == 0) {
        float tot = 0.f;
#pragma unroll
        for (int p = 0; p < 8; p++) tot += red[p];
        parts[bid] = tot;
    }

    // ---- Hermitian unpack: one thread per (pair,k) writes both rows as one STG.64 ----
    int p      = tid & 3;
    int kslot  = tid >> 2;
    __half2* so = smB[p];
    size_t dbase = ((size_t)b << 9) + r0 + 2 * p;
#pragma unroll
    for (int it = 0; it < 5; it++) {
        int k = kslot + (it << 6);
        if (k < NFREQ) {
            float2 z = __half22float2(so[adr2(k)]);
            float2 y = __half22float2(so[adr2((512 - k) & 511)]);
            __half2 A = __floats2half2_rn(0.5f * (z.x + y.x), 0.5f * (z.y - y.y));
            __half2 B = __floats2half2_rn(0.5f * (z.y + y.y), 0.5f * (y.x - z.x));
            F2U pack; ((__half2*)&pack.u)[0] = A; ((__half2*)&pack.u)[1] = B;
            *reinterpret_cast<unsigned long long*>(
                &dst[(size_t)k * kstride + dbase]) = pack.u;
        }
    }
}

// ---------------- kernel 2: DIF column FFTs — 4 cols x 8 images, fp16 everywhere -------------
__global__ void __launch_bounds__(256, 4) k_colfft() {
    __shared__ __half2 smbuf[2][4][576];   // double-buffered stage-0 output, fp16
    __shared__ float smean[8];
    int ct  = blockIdx.x % 65;
    int grp = blockIdx.x / 65;             // 0..15 : 8 images each
    int f   = threadIdx.x >> 6;
    int tau = threadIdx.x & 63;
    int g   = tau >> 3, jj = tau & 7;
    int c   = (ct << 2) + f;
    bool valid = (c < NFREQ);
    size_t cbase = valid ? (size_t)c * RS : 0;
    int b0 = grp << 3;
    int bar = f + 1;

    // ---- cached correction vector (invariant over image loop), fp32 in regs ----
    float2 hv[8];
    size_t hbase = valid ? ((size_t)c << 9) : 0;
#pragma unroll
    for (int m = 0; m < 8; m++)
        hv[m] = valid ? __half22float2(g_hrow[hbase + tau + (m << 6)])
                      : make_float2(0.f, 0.f);

    // ---- prefetch image 0 (raw fp16, converted at use) ----
    __half2 traw[8];
#pragma unroll
    for (int m = 0; m < 8; m++)
        traw[m] = valid ? g_scratch[cbase + ((size_t)b0 << 9) + tau + (m << 6)]
                        : __half2(__float2half2_rn(0.f));

    // ---- fused per-image means: warp w reduces image b0+w ----
    {
        int w = threadIdx.x >> 5, l = threadIdx.x & 31;
        float v = g_parts[((b0 + w) << 6) + l] + g_parts[((b0 + w) << 6) + 32 + l];
#pragma unroll
        for (int o = 16; o; o >>= 1) v += __shfl_down_sync(0xffffffffu, v, o);
        if (l == 0) smean[w] = v * (1.0f / 262144.0f);
        __syncthreads();
    }

    int pbS = tau + (tau >> 3);
    int pbL = 72 * g + jj;
    int e1 = jj << 3;

    float acc[8];
#pragma unroll
    for (int m = 0; m < 8; m++) acc[m] = 0.f;

    for (int bi = 0; bi < 8; bi++) {
        float mean = smean[bi];
        __half2* s = smbuf[bi & 1][f];

        // stage 0 (registers): convert + mean correction + dft8 + twiddle
        float2 tc[8];
#pragma unroll
        for (int m = 0; m < 8; m++) {
            float2 v = __half22float2(traw[m]);
            tc[m] = make_float2(fmaf(-mean, hv[m].x, v.x),
                                fmaf(-mean, hv[m].y, v.y));
        }
        dft8(tc);
#pragma unroll
        for (int q = 1; q < 8; q++) tc[q] = cmulf2(tc[q], g_tw[tau * q]);
#pragma unroll
        for (int q = 0; q < 8; q++)
            s[pbS + 72 * q] = __floats2half2_rn(tc[q].x, tc[q].y);

        // prefetch next image into dead traw — hidden across barrier + stages 1-2
        if (bi < 7 && valid) {
            int b = b0 + bi + 1;
#pragma unroll
            for (int m = 0; m < 8; m++)
                traw[m] = g_scratch[cbase + ((size_t)b << 9) + tau + (m << 6)];
        }
        BARSYNC(bar);     // data-ready; WAR vs image bi-2 guaranteed by double buffer

        // stage 1 in registers
        float2 u[8];
#pragma unroll
        for (int m = 0; m < 8; m++) u[m] = __half22float2(s[pbL + 9 * m]);
        dft8(u);
#pragma unroll
        for (int q = 1; q < 8; q++) u[q] = cmulf2(u[q], g_tw[e1 * q]);

        // fp16 shuffle exchange + stage 2 + accumulate
        unsigned int uh[8];
#pragma unroll
        for (int q = 0; q < 8; q++) { HU h; h.h = __floats2half2_rn(u[q].x, u[q].y); uh[q] = h.u; }
        transpose8h(uh, jj);
#pragma unroll
        for (int m = 0; m < 8; m++) { HU h; h.u = uh[m]; u[m] = __half22float2(h.h); }
        dft8(u);
#pragma unroll
        for (int m = 0; m < 8; m++)
            acc[m] = fmaf(u[m].x, u[m].x, fmaf(u[m].y, u[m].y, acc[m]));
    }

    if (valid) {
        int rlo = (jj << 3) + g;
#pragma unroll
        for (int m = 0; m < 8; m++) {
            int r = (m << 6) + rlo;            // natural frequency index
            atomicAdd(&g_accum[r * NFREQ + c], acc[m]);
        }
    }
}

// ---------------- kernel 3: nps2D + two-level radial binning ---------------------------------
__global__ void __launch_bounds__(256) k_finalize2d(float* __restrict__ out) {
    __shared__ float ssum[NFREQ];
    __shared__ float scnt[NFREQ];
    int i = blockIdx.x;
    int tid = threadIdx.x;
    if (tid < NFREQ) { ssum[tid] = 0.f; scnt[tid] = 0.f; }
    if (tid + 256 < NFREQ) { ssum[tid + 256] = 0.f; scnt[tid + 256] = 0.f; }
    __syncthreads();

    const float SC = (float)(0.01 / (262144.0 * 128.0));
    int xi = i - 256;
#pragma unroll
    for (int h = 0; h < 2; h++) {
        int j = tid + (h << 8);
        int u = i ^ 256, v = j ^ 256;
        if (v > 256) { u = (512 - u) & 511; v = 512 - v; }
        float val = g_accum[u * NFREQ + v] * SC;
        out[NFREQ + (i << 9) + j] = val;
        int yj = j - 256;
        int rad = __float2int_rn(__fsqrt_rn((float)(xi * xi + yj * yj)));
        if (rad < NFREQ) {
            atomicAdd(&ssum[rad], val);
            atomicAdd(&scnt[rad], 1.0f);
        }
    }
    __syncthreads();

    int part = i & 31;
    if (tid < NFREQ && (ssum[tid] != 0.f || scnt[tid] != 0.f)) {
        atomicAdd(&g_psum[part][tid], ssum[tid]);
        atomicAdd(&g_pcnt[part][tid], scnt[tid]);
    }
    if (tid + 256 < NFREQ && (ssum[tid + 256] != 0.f || scnt[tid + 256] != 0.f)) {
        atomicAdd(&g_psum[part][tid + 256], ssum[tid + 256]);
        atomicAdd(&g_pcnt[part][tid + 256], scnt[tid + 256]);
    }
}

// ---------------- kernel 4: nps1D and f1D ----------------------------------------------------
__global__ void k_finalize1d(float* __restrict__ out) {
    int k = threadIdx.x;
    if (k < NFREQ) {
        float s = 0.f, c = 0.f;
#pragma unroll
        for (int p = 0; p < 32; p++) { s += g_psum[p][k]; c += g_pcnt[p][k]; }
        out[k] = s / c;
        out[NFREQ + N * N + k] = 5.0f * (float)k / 256.0f;
    }
}

extern "C" void kernel_launch(void* const* d_in, const int* in_sizes, int n_in,
                              void* d_out, int out_size) {
    const float* x = (const float*)d_in[0];
    float* out = (float*)d_out;

    k_init<<<1024, 256>>>();
    k_rowfft<<<NIMG * 64 + 64, 256>>>(x);      // images + window FFT in one grid
    k_colfft<<<65 * 16, 256>>>();              // 4 cols x 8 images per block
    k_finalize2d<<<N, 256>>>(out);
    k_finalize1d<<<1, NFREQ>>>(out);
}

// round 12
// speedup vs baseline: 1.6578x; 1.2494x over previous
#include <cuda_runtime.h>
#include <cuda_fp16.h>
#include <math.h>

#define N 512
#define NIMG 128
#define NFREQ 257
#define RS 65536                 // image scratch k-stride in half2 (=128*512)

#define BARSYNC(id) asm volatile("bar.sync %0, 64;" :: "r"(id) : "memory")

// ---------------- device scratch ------------------------------------------------------------
static __device__ __half2 g_scratch[(size_t)NFREQ * RS];  // c-major: [k][b*512+r], ~67MB, fp16
static __device__ __half2 g_hrow[(size_t)NFREQ * N];      // rowFFT of hann, [k][r], 0.5MB
static __device__ float2  g_tw[N];                        // W_512^k
static __device__ __half2 g_hann2[256 * 512];             // hann pairs (row r, r+1), 0.5MB
static __device__ float   g_parts[NIMG * 64];
static __device__ float   g_hparts[64];
static __device__ float   g_accum[N * NFREQ];             // half-plane sum |F|^2 (unshifted)
static __device__ float   g_psum[32][NFREQ];
static __device__ float   g_pcnt[32][NFREQ];

__device__ __forceinline__ int adr2(int i) { return i + (i >> 3); }

// ---- packed helpers ---------------------------------------------------------------------
union F2U { float2 f; unsigned long long u; };
union HU  { __half2 h; unsigned int u; };
__device__ __forceinline__ float2 padd(float2 a, float2 b) {
    F2U A, B, C; A.f = a; B.f = b;
    asm("add.rn.f32x2 %0, %1, %2;" : "=l"(C.u) : "l"(A.u), "l"(B.u));
    return C.f;
}
__device__ __forceinline__ float2 psub(float2 a, float2 b) {
    F2U A, B, C; A.f = a; B.f = b;
    asm("fma.rn.f32x2 %0, %1, %2, %3;"
        : "=l"(C.u) : "l"(B.u), "l"(0xBF800000BF800000ULL), "l"(A.u));
    return C.f;
}
__device__ __forceinline__ float2 cmulf2(float2 a, float2 w) {
    return make_float2(a.x * w.x - a.y * w.y, a.x * w.y + a.y * w.x);
}

// ---- natural-order 8-point DFT --------------------------------------------------------------
__device__ __forceinline__ void dft8(float2* t) {
    float2 b0 = t[0], b1 = t[4], b2 = t[2], b3 = t[6];
    float2 b4 = t[1], b5 = t[5], b6 = t[3], b7 = t[7];
    float2 u0 = padd(b0, b1), u1 = psub(b0, b1), u2 = padd(b2, b3), u3 = psub(b2, b3);
    float2 u4 = padd(b4, b5), u5 = psub(b4, b5), u6 = padd(b6, b7), u7 = psub(b6, b7);
    float2 v0 = padd(u0, u2), v2 = psub(u0, u2);
    float2 v1 = make_float2(u1.x + u3.y, u1.y - u3.x);
    float2 v3 = make_float2(u1.x - u3.y, u1.y + u3.x);
    float2 v4 = padd(u4, u6), v6 = psub(u4, u6);
    float2 v5 = make_float2(u5.x + u7.y, u5.y - u7.x);
    float2 v7 = make_float2(u5.x - u7.y, u5.y + u7.x);
    const float C = 0.70710678118654752f;
    float2 a5 = make_float2(C * (v5.x + v5.y), C * (v5.y - v5.x));
    float2 a7 = make_float2(C * (v7.y - v7.x), -C * (v7.x + v7.y));
    t[0] = padd(v0, v4); t[4] = psub(v0, v4);
    t[1] = padd(v1, a5); t[5] = psub(v1, a5);
    t[2] = make_float2(v2.x + v6.y, v2.y - v6.x);
    t[6] = make_float2(v2.x - v6.y, v2.y + v6.x);
    t[3] = padd(v3, a7); t[7] = psub(v3, a7);
}

// ---- apply geometric twiddle chain: t[q] *= w^q, q=1..7 (6 cmuls from one base) --------------
__device__ __forceinline__ void twiddle_chain(float2* t, float2 w) {
    float2 wq = w;
    t[1] = cmulf2(t[1], wq);
#pragma unroll
    for (int q = 2; q < 8; q++) {
        wq = cmulf2(wq, w);
        t[q] = cmulf2(t[q], wq);
    }
}

// ---- 8x8 half2 transpose across 8 lanes (SHFL.32, 3 rounds) ---------------------------------
__device__ __forceinline__ void transpose8h(unsigned int* u, int jj) {
#pragma unroll
    for (int k = 0; k < 3; k++) {
        const int m = 1 << k;
        bool hi = (jj & m) != 0;
#pragma unroll
        for (int i0 = 0; i0 < 8; i0++) {
            if ((i0 & m) == 0) {
                int i1 = i0 | m;
                unsigned int snd = hi ? u[i0] : u[i1];
                unsigned int rcv = __shfl_xor_sync(0xffffffffu, snd, m);
                if (hi) u[i0] = rcv; else u[i1] = rcv;
            }
        }
    }
}

// ---------------- kernel 0: init (twiddles, hann pairs, zero accumulators) -------------------
__global__ void k_init() {
    int p = blockIdx.x * blockDim.x + threadIdx.x;   // 0..262143
    if (p < 256 * 512) {   // hann pair table: rows 2rp, 2rp+1 at column j
        int rp = p >> 9, j = p & 511;
        const float STEP = 512.0f / 511.0f;
        float lc = fmaf((float)j, STEP, -256.0f);
        float h0, h1;
        {
            float lr = fmaf((float)(2 * rp), STEP, -256.0f);
            float rd = sqrtf(lc * lc + lr * lr);
            h0 = (rd > 256.0f) ? 0.0f : 0.5f * (1.0f + cospif(rd * (1.0f / 256.0f)));
        }
        {
            float lr = fmaf((float)(2 * rp + 1), STEP, -256.0f);
            float rd = sqrtf(lc * lc + lr * lr);
            h1 = (rd > 256.0f) ? 0.0f : 0.5f * (1.0f + cospif(rd * (1.0f / 256.0f)));
        }
        g_hann2[p] = __floats2half2_rn(h0, h1);
    }
    if (p < N * NFREQ) g_accum[p] = 0.f;
    if (p < N) {
        double ang = -6.283185307179586476925286766559 * (double)p / 512.0;
        g_tw[p] = make_float2((float)cos(ang), (float)sin(ang));
    }
    if (p < 32 * NFREQ) { ((float*)g_psum)[p] = 0.f; ((float*)g_pcnt)[p] = 0.f; }
}

// ---------------- kernel 1: DIF row FFTs (images + window in one grid) ------------------------
__global__ void __launch_bounds__(256) k_rowfft(const float* __restrict__ src) {
    __shared__ __half2 smA[4][576];    // stage-0 output (fp16)
    __shared__ __half2 smB[4][576];    // final spectrum, natural freq index (fp16)
    __shared__ float red[8];
    bool win = blockIdx.x >= NIMG * 64;
    int bid  = win ? (int)blockIdx.x - NIMG * 64 : (int)blockIdx.x;
    int b    = win ? 0 : (bid >> 6);
    int r0   = (win ? bid : (bid & 63)) << 3;
    __half2* dst = win ? g_hrow : g_scratch;
    int kstride  = win ? N : RS;
    float* parts = win ? g_hparts : g_parts;

    int tid = threadIdx.x;
    int f   = tid >> 6, tau = tid & 63;
    int g   = tau >> 3, jj = tau & 7;
    int rowA = r0 + 2 * f;
    size_t srcbase = ((size_t)b << 18) + ((size_t)rowA << 9);
    const __half2* hP = g_hann2 + ((rowA >> 1) << 9);
    __half2* sA = smA[f];
    __half2* sB = smB[f];
    float2 w0 = g_tw[tau];        // W^tau  (stage-0 chain base)
    float2 w1 = g_tw[jj << 3];    // W^(8jj) (stage-1 chain base)

    // ---- load + stage 0 (stride 64) in registers ----
    float2 t[8];
    float lsum = 0.f;
#pragma unroll
    for (int m = 0; m < 8; m++) {
        int c = tau + (m << 6);
        float2 h2 = __half22float2(hP[c]);
        float va = 1.0f, vb = 1.0f;
        if (!win) {
            va = src[srcbase + c];
            vb = src[srcbase + 512 + c];
            lsum += va + vb;
        }
        t[m] = make_float2(va * h2.x, vb * h2.y);
    }
    dft8(t);
    twiddle_chain(t, w0);
    int pbS = tau + (tau >> 3);
#pragma unroll
    for (int q = 0; q < 8; q++) sA[pbS + 72 * q] = __floats2half2_rn(t[q].x, t[q].y);

    // per-warp pixel sums (consumed after the final block barrier)
#pragma unroll
    for (int o = 16; o; o >>= 1) lsum += __shfl_down_sync(0xffffffffu, lsum, o);
    if ((tid & 31) == 0) red[tid >> 5] = lsum;
    __syncthreads();

    // ---- stage 1 (stride 8) in registers ----
    float2 u[8];
    int pbL = 72 * g + jj;
#pragma unroll
    for (int m = 0; m < 8; m++) u[m] = __half22float2(sA[pbL + 9 * m]);
    dft8(u);
    twiddle_chain(u, w1);

    // ---- fp16 shuffle exchange + stage 2 ----
    unsigned int uh[8];
#pragma unroll
    for (int q = 0; q < 8; q++) { HU h; h.h = __floats2half2_rn(u[q].x, u[q].y); uh[q] = h.u; }
    transpose8h(uh, jj);
#pragma unroll
    for (int m = 0; m < 8; m++) { HU h; h.u = uh[m]; u[m] = __half22float2(h.h); }
    dft8(u);

    // store at natural frequency index (fp16)
#pragma unroll
    for (int m = 0; m < 8; m++)
        sB[adr2((m << 6) + (jj << 3) + g)] = __floats2half2_rn(u[m].x, u[m].y);
    __syncthreads();

    if (tid == 0) {
        float tot = 0.f;
#pragma unroll
        for (int p = 0; p < 8; p++) tot += red[p];
        parts[bid] = tot;
    }

    // ---- Hermitian unpack: one thread per (pair,k) writes both rows as one STG.64 ----
    int p      = tid & 3;
    int kslot  = tid >> 2;
    __half2* so = smB[p];
    size_t dbase = ((size_t)b << 9) + r0 + 2 * p;
#pragma unroll
    for (int it = 0; it < 5; it++) {
        int k = kslot + (it << 6);
        if (k < NFREQ) {
            float2 z = __half22float2(so[adr2(k)]);
            float2 y = __half22float2(so[adr2((512 - k) & 511)]);
            __half2 A = __floats2half2_rn(0.5f * (z.x + y.x), 0.5f * (z.y - y.y));
            __half2 B = __floats2half2_rn(0.5f * (z.y + y.y), 0.5f * (y.x - z.x));
            F2U pack; ((__half2*)&pack.u)[0] = A; ((__half2*)&pack.u)[1] = B;
            *reinterpret_cast<unsigned long long*>(
                &dst[(size_t)k * kstride + dbase]) = pack.u;
        }
    }
}

// ---------------- kernel 2: DIF column FFTs — 4 cols x 8 images, register twiddles ------------
__global__ void __launch_bounds__(256, 4) k_colfft() {
    __shared__ __half2 smbuf[2][4][576];   // double-buffered stage-0 output, fp16
    __shared__ float smean[8];
    int ct  = blockIdx.x % 65;
    int grp = blockIdx.x / 65;             // 0..15 : 8 images each
    int f   = threadIdx.x >> 6;
    int tau = threadIdx.x & 63;
    int g   = tau >> 3, jj = tau & 7;
    int c   = (ct << 2) + f;
    bool valid = (c < NFREQ);
    size_t cbase = valid ? (size_t)c * RS : 0;
    int b0 = grp << 3;
    int bar = f + 1;
    float2 w0 = g_tw[tau];        // hoisted chain bases (loop-invariant)
    float2 w1 = g_tw[jj << 3];

    // ---- cached correction vector (invariant over image loop), fp32 in regs ----
    float2 hv[8];
    size_t hbase = valid ? ((size_t)c << 9) : 0;
#pragma unroll
    for (int m = 0; m < 8; m++)
        hv[m] = valid ? __half22float2(g_hrow[hbase + tau + (m << 6)])
                      : make_float2(0.f, 0.f);

    // ---- prefetch image 0 (raw fp16, converted at use) ----
    __half2 traw[8];
#pragma unroll
    for (int m = 0; m < 8; m++)
        traw[m] = valid ? g_scratch[cbase + ((size_t)b0 << 9) + tau + (m << 6)]
                        : __half2(__float2half2_rn(0.f));

    // ---- fused per-image means: warp w reduces image b0+w ----
    {
        int w = threadIdx.x >> 5, l = threadIdx.x & 31;
        float v = g_parts[((b0 + w) << 6) + l] + g_parts[((b0 + w) << 6) + 32 + l];
#pragma unroll
        for (int o = 16; o; o >>= 1) v += __shfl_down_sync(0xffffffffu, v, o);
        if (l == 0) smean[w] = v * (1.0f / 262144.0f);
        __syncthreads();
    }

    int pbS = tau + (tau >> 3);
    int pbL = 72 * g + jj;

    float acc[8];
#pragma unroll
    for (int m = 0; m < 8; m++) acc[m] = 0.f;

    for (int bi = 0; bi < 8; bi++) {
        float mean = smean[bi];
        __half2* s = smbuf[bi & 1][f];

        // stage 0 (registers): convert + mean correction + dft8 + twiddle chain
        float2 tc[8];
#pragma unroll
        for (int m = 0; m < 8; m++) {
            float2 v = __half22float2(traw[m]);
            tc[m] = make_float2(fmaf(-mean, hv[m].x, v.x),
                                fmaf(-mean, hv[m].y, v.y));
        }
        dft8(tc);
        twiddle_chain(tc, w0);
#pragma unroll
        for (int q = 0; q < 8; q++)
            s[pbS + 72 * q] = __floats2half2_rn(tc[q].x, tc[q].y);

        // prefetch next image into dead traw — hidden across barrier + stages 1-2
        if (bi < 7 && valid) {
            int b = b0 + bi + 1;
#pragma unroll
            for (int m = 0; m < 8; m++)
                traw[m] = g_scratch[cbase + ((size_t)b << 9) + tau + (m << 6)];
        }
        BARSYNC(bar);     // data-ready; WAR vs image bi-2 guaranteed by double buffer

        // stage 1 in registers
        float2 u[8];
#pragma unroll
        for (int m = 0; m < 8; m++) u[m] = __half22float2(s[pbL + 9 * m]);
        dft8(u);
        twiddle_chain(u, w1);

        // fp16 shuffle exchange + stage 2 + accumulate
        unsigned int uh[8];
#pragma unroll
        for (int q = 0; q < 8; q++) { HU h; h.h = __floats2half2_rn(u[q].x, u[q].y); uh[q] = h.u; }
        transpose8h(uh, jj);
#pragma unroll
        for (int m = 0; m < 8; m++) { HU h; h.u = uh[m]; u[m] = __half22float2(h.h); }
        dft8(u);
#pragma unroll
        for (int m = 0; m < 8; m++)
            acc[m] = fmaf(u[m].x, u[m].x, fmaf(u[m].y, u[m].y, acc[m]));
    }

    if (valid) {
        int rlo = (jj << 3) + g;
#pragma unroll
        for (int m = 0; m < 8; m++) {
            int r = (m << 6) + rlo;            // natural frequency index
            atomicAdd(&g_accum[r * NFREQ + c], acc[m]);
        }
    }
}

// ---------------- kernel 3: nps2D + two-level radial binning ---------------------------------
__global__ void __launch_bounds__(256) k_finalize2d(float* __restrict__ out) {
    __shared__ float ssum[NFREQ];
    __shared__ float scnt[NFREQ];
    int i = blockIdx.x;
    int tid = threadIdx.x;
    if (tid < NFREQ) { ssum[tid] = 0.f; scnt[tid] = 0.f; }
    if (tid + 256 < NFREQ) { ssum[tid + 256] = 0.f; scnt[tid + 256] = 0.f; }
    __syncthreads();

    const float SC = (float)(0.01 / (262144.0 * 128.0));
    int xi = i - 256;
#pragma unroll
    for (int h = 0; h < 2; h++) {
        int j = tid + (h << 8);
        int u = i ^ 256, v = j ^ 256;
        if (v > 256) { u = (512 - u) & 511; v = 512 - v; }
        float val = g_accum[u * NFREQ + v] * SC;
        out[NFREQ + (i << 9) + j] = val;
        int yj = j - 256;
        int rad = __float2int_rn(__fsqrt_rn((float)(xi * xi + yj * yj)));
        if (rad < NFREQ) {
            atomicAdd(&ssum[rad], val);
            atomicAdd(&scnt[rad], 1.0f);
        }
    }
    __syncthreads();

    int part = i & 31;
    if (tid < NFREQ && (ssum[tid] != 0.f || scnt[tid] != 0.f)) {
        atomicAdd(&g_psum[part][tid], ssum[tid]);
        atomicAdd(&g_pcnt[part][tid], scnt[tid]);
    }
    if (tid + 256 < NFREQ && (ssum[tid + 256] != 0.f || scnt[tid + 256] != 0.f)) {
        atomicAdd(&g_psum[part][tid + 256], ssum[tid + 256]);
        atomicAdd(&g_pcnt[part][tid + 256], scnt[tid + 256]);
    }
}

// ---------------- kernel 4: nps1D and f1D ----------------------------------------------------
__global__ void k_finalize1d(float* __restrict__ out) {
    int k = threadIdx.x;
    if (k < NFREQ) {
        float s = 0.f, c = 0.f;
#pragma unroll
        for (int p = 0; p < 32; p++) { s += g_psum[p][k]; c += g_pcnt[p][k]; }
        out[k] = s / c;
        out[NFREQ + N * N + k] = 5.0f * (float)k / 256.0f;
    }
}

extern "C" void kernel_launch(void* const* d_in, const int* in_sizes, int n_in,
                              void* d_out, int out_size) {
    const float* x = (const float*)d_in[0];
    float* out = (float*)d_out;

    k_init<<<1024, 256>>>();
    k_rowfft<<<NIMG * 64 + 64, 256>>>(x);      // images + window FFT in one grid
    k_colfft<<<65 * 16, 256>>>();              // 4 cols x 8 images per block
    k_finalize2d<<<N, 256>>>(out);
    k_finalize1d<<<1, NFREQ>>>(out);
}

// round 13
// speedup vs baseline: 1.6623x; 1.0027x over previous
#include <cuda_runtime.h>
#include <cuda_fp16.h>
#include <math.h>

#define N 512
#define NIMG 128
#define NFREQ 257
#define RS 65536                 // image scratch k-stride in half2 (=128*512)
#define GIMG 4                   // images per rowfft block

#define BARSYNC(id) asm volatile("bar.sync %0, 64;" :: "r"(id) : "memory")

// ---------------- device scratch ------------------------------------------------------------
static __device__ __half2 g_scratch[(size_t)NFREQ * RS];  // c-major: [k][b*512+r], ~67MB, fp16
static __device__ __half2 g_hrow[(size_t)NFREQ * N];      // rowFFT of hann, [k][r], 0.5MB
static __device__ float2  g_tw[N];                        // W_512^k
static __device__ __half2 g_hann2[256 * 512];             // hann pairs (row r, r+1), 0.5MB
static __device__ float   g_parts[NIMG * 64];
static __device__ float   g_hparts[64];
static __device__ float   g_accum[N * NFREQ];             // half-plane sum |F|^2 (unshifted)
static __device__ float   g_psum[32][NFREQ];
static __device__ float   g_pcnt[32][NFREQ];

__device__ __forceinline__ int adr2(int i) { return i + (i >> 3); }

// ---- packed helpers ---------------------------------------------------------------------
union F2U { float2 f; unsigned long long u; };
union HU  { __half2 h; unsigned int u; };
__device__ __forceinline__ float2 padd(float2 a, float2 b) {
    F2U A, B, C; A.f = a; B.f = b;
    asm("add.rn.f32x2 %0, %1, %2;" : "=l"(C.u) : "l"(A.u), "l"(B.u));
    return C.f;
}
__device__ __forceinline__ float2 psub(float2 a, float2 b) {
    F2U A, B, C; A.f = a; B.f = b;
    asm("fma.rn.f32x2 %0, %1, %2, %3;"
        : "=l"(C.u) : "l"(B.u), "l"(0xBF800000BF800000ULL), "l"(A.u));
    return C.f;
}
__device__ __forceinline__ float2 cmulf2(float2 a, float2 w) {
    return make_float2(a.x * w.x - a.y * w.y, a.x * w.y + a.y * w.x);
}

// ---- natural-order 8-point DFT --------------------------------------------------------------
__device__ __forceinline__ void dft8(float2* t) {
    float2 b0 = t[0], b1 = t[4], b2 = t[2], b3 = t[6];
    float2 b4 = t[1], b5 = t[5], b6 = t[3], b7 = t[7];
    float2 u0 = padd(b0, b1), u1 = psub(b0, b1), u2 = padd(b2, b3), u3 = psub(b2, b3);
    float2 u4 = padd(b4, b5), u5 = psub(b4, b5), u6 = padd(b6, b7), u7 = psub(b6, b7);
    float2 v0 = padd(u0, u2), v2 = psub(u0, u2);
    float2 v1 = make_float2(u1.x + u3.y, u1.y - u3.x);
    float2 v3 = make_float2(u1.x - u3.y, u1.y + u3.x);
    float2 v4 = padd(u4, u6), v6 = psub(u4, u6);
    float2 v5 = make_float2(u5.x + u7.y, u5.y - u7.x);
    float2 v7 = make_float2(u5.x - u7.y, u5.y + u7.x);
    const float C = 0.70710678118654752f;
    float2 a5 = make_float2(C * (v5.x + v5.y), C * (v5.y - v5.x));
    float2 a7 = make_float2(C * (v7.y - v7.x), -C * (v7.x + v7.y));
    t[0] = padd(v0, v4); t[4] = psub(v0, v4);
    t[1] = padd(v1, a5); t[5] = psub(v1, a5);
    t[2] = make_float2(v2.x + v6.y, v2.y - v6.x);
    t[6] = make_float2(v2.x - v6.y, v2.y + v6.x);
    t[3] = padd(v3, a7); t[7] = psub(v3, a7);
}

// ---- apply geometric twiddle chain: t[q] *= w^q, q=1..7 --------------------------------------
__device__ __forceinline__ void twiddle_chain(float2* t, float2 w) {
    float2 wq = w;
    t[1] = cmulf2(t[1], wq);
#pragma unroll
    for (int q = 2; q < 8; q++) {
        wq = cmulf2(wq, w);
        t[q] = cmulf2(t[q], wq);
    }
}

// ---- 8x8 half2 transpose across 8 lanes (SHFL.32, 3 rounds) ---------------------------------
__device__ __forceinline__ void transpose8h(unsigned int* u, int jj) {
#pragma unroll
    for (int k = 0; k < 3; k++) {
        const int m = 1 << k;
        bool hi = (jj & m) != 0;
#pragma unroll
        for (int i0 = 0; i0 < 8; i0++) {
            if ((i0 & m) == 0) {
                int i1 = i0 | m;
                unsigned int snd = hi ? u[i0] : u[i1];
                unsigned int rcv = __shfl_xor_sync(0xffffffffu, snd, m);
                if (hi) u[i0] = rcv; else u[i1] = rcv;
            }
        }
    }
}

// ---------------- kernel 0: init (twiddles, hann pairs, zero accumulators) -------------------
__global__ void k_init() {
    int p = blockIdx.x * blockDim.x + threadIdx.x;   // 0..262143
    if (p < 256 * 512) {
        int rp = p >> 9, j = p & 511;
        const float STEP = 512.0f / 511.0f;
        float lc = fmaf((float)j, STEP, -256.0f);
        float h0, h1;
        {
            float lr = fmaf((float)(2 * rp), STEP, -256.0f);
            float rd = sqrtf(lc * lc + lr * lr);
            h0 = (rd > 256.0f) ? 0.0f : 0.5f * (1.0f + cospif(rd * (1.0f / 256.0f)));
        }
        {
            float lr = fmaf((float)(2 * rp + 1), STEP, -256.0f);
            float rd = sqrtf(lc * lc + lr * lr);
            h1 = (rd > 256.0f) ? 0.0f : 0.5f * (1.0f + cospif(rd * (1.0f / 256.0f)));
        }
        g_hann2[p] = __floats2half2_rn(h0, h1);
    }
    if (p < N * NFREQ) g_accum[p] = 0.f;
    if (p < N) {
        double ang = -6.283185307179586476925286766559 * (double)p / 512.0;
        g_tw[p] = make_float2((float)cos(ang), (float)sin(ang));
    }
    if (p < 32 * NFREQ) { ((float*)g_psum)[p] = 0.f; ((float*)g_pcnt)[p] = 0.f; }
}

// ---------------- kernel 1: DIF row FFTs, GIMG images per block (window blocks: 1) ------------
// blocks 0..2047: image mode (rgrp = bid&63, igrp = bid>>6, images igrp*4..+3)
// blocks 2048..2111: window mode (one pass, src = 1)
__global__ void __launch_bounds__(256) k_rowfft(const float* __restrict__ src) {
    __shared__ __half2 smA[4][576];
    __shared__ __half2 smB[4][576];
    __shared__ float red[8];
    bool win = blockIdx.x >= 2048;
    int rgrp = win ? (int)blockIdx.x - 2048 : (int)blockIdx.x & 63;
    int igrp = win ? 0 : (int)blockIdx.x >> 6;
    int r0   = rgrp << 3;
    __half2* dst = win ? g_hrow : g_scratch;
    int kstride  = win ? N : RS;
    int niter    = win ? 1 : GIMG;

    int tid = threadIdx.x;
    int f   = tid >> 6, tau = tid & 63;
    int g   = tau >> 3, jj = tau & 7;
    int rowA = r0 + 2 * f;
    const __half2* hP = g_hann2 + ((rowA >> 1) << 9);
    __half2* sA = smA[f];
    __half2* sB = smB[f];
    float2 w0 = g_tw[tau];
    float2 w1 = g_tw[jj << 3];
    int pbS = tau + (tau >> 3);
    int pbL = 72 * g + jj;

    // ---- cache hann pairs for this block's 8 rows (invariant over images) ----
    __half2 hreg[8];
#pragma unroll
    for (int m = 0; m < 8; m++) hreg[m] = hP[tau + (m << 6)];

    for (int it = 0; it < niter; it++) {
        int b = (igrp << 2) + it;
        size_t srcbase = ((size_t)b << 18) + ((size_t)rowA << 9);

        // ---- load + stage 0 (stride 64) in registers ----
        float2 t[8];
        float lsum = 0.f;
#pragma unroll
        for (int m = 0; m < 8; m++) {
            int c = tau + (m << 6);
            float2 h2 = __half22float2(hreg[m]);
            float va = 1.0f, vb = 1.0f;
            if (!win) {
                va = src[srcbase + c];
                vb = src[srcbase + 512 + c];
                lsum += va + vb;
            }
            t[m] = make_float2(va * h2.x, vb * h2.y);
        }
        dft8(t);
        twiddle_chain(t, w0);
#pragma unroll
        for (int q = 0; q < 8; q++) sA[pbS + 72 * q] = __floats2half2_rn(t[q].x, t[q].y);

        // warp-reduce pixel sums into registers (red[] written only after sync1)
#pragma unroll
        for (int o = 16; o; o >>= 1) lsum += __shfl_down_sync(0xffffffffu, lsum, o);
        __syncthreads();                        // sync1: smA ready; prev red consumed
        if ((tid & 31) == 0) red[tid >> 5] = lsum;

        // ---- stage 1 (stride 8) in registers ----
        float2 u[8];
#pragma unroll
        for (int m = 0; m < 8; m++) u[m] = __half22float2(sA[pbL + 9 * m]);
        dft8(u);
        twiddle_chain(u, w1);

        // ---- fp16 shuffle exchange + stage 2 ----
        unsigned int uh[8];
#pragma unroll
        for (int q = 0; q < 8; q++) { HU h; h.h = __floats2half2_rn(u[q].x, u[q].y); uh[q] = h.u; }
        transpose8h(uh, jj);
#pragma unroll
        for (int m = 0; m < 8; m++) { HU h; h.u = uh[m]; u[m] = __half22float2(h.h); }
        dft8(u);

#pragma unroll
        for (int m = 0; m < 8; m++)
            sB[adr2((m << 6) + (jj << 3) + g)] = __floats2half2_rn(u[m].x, u[m].y);
        __syncthreads();                        // sync2: smB + red ready

        if (tid == 0) {
            float tot = 0.f;
#pragma unroll
            for (int p = 0; p < 8; p++) tot += red[p];
            if (win) g_hparts[rgrp] = tot;
            else     g_parts[(b << 6) + rgrp] = tot;
        }

        // ---- Hermitian unpack: one thread per (pair,k) writes both rows as one STG.64 ----
        int p      = tid & 3;
        int kslot  = tid >> 2;
        __half2* so = smB[p];
        size_t dbase = ((size_t)b << 9) + r0 + 2 * p;
        if (win) dbase = r0 + 2 * p;
#pragma unroll
        for (int kk = 0; kk < 5; kk++) {
            int k = kslot + (kk << 6);
            if (k < NFREQ) {
                float2 z = __half22float2(so[adr2(k)]);
                float2 y = __half22float2(so[adr2((512 - k) & 511)]);
                __half2 A = __floats2half2_rn(0.5f * (z.x + y.x), 0.5f * (z.y - y.y));
                __half2 B = __floats2half2_rn(0.5f * (z.y + y.y), 0.5f * (y.x - z.x));
                F2U pack; ((__half2*)&pack.u)[0] = A; ((__half2*)&pack.u)[1] = B;
                *reinterpret_cast<unsigned long long*>(
                    &dst[(size_t)k * kstride + dbase]) = pack.u;
            }
        }
    }
}

// ---------------- kernel 2: DIF column FFTs — 4 cols x 8 images, HFMA2 correction -------------
__global__ void __launch_bounds__(256, 4) k_colfft() {
    __shared__ __half2 smbuf[2][4][576];
    __shared__ float smean[8];
    int ct  = blockIdx.x % 65;
    int grp = blockIdx.x / 65;             // 0..15 : 8 images each
    int f   = threadIdx.x >> 6;
    int tau = threadIdx.x & 63;
    int g   = tau >> 3, jj = tau & 7;
    int c   = (ct << 2) + f;
    bool valid = (c < NFREQ);
    size_t cbase = valid ? (size_t)c * RS : 0;
    int b0 = grp << 3;
    int bar = f + 1;
    float2 w0 = g_tw[tau];
    float2 w1 = g_tw[jj << 3];

    // ---- cached correction vector (fp16 regs, invariant over image loop) ----
    __half2 hvh[8];
    size_t hbase = valid ? ((size_t)c << 9) : 0;
#pragma unroll
    for (int m = 0; m < 8; m++)
        hvh[m] = valid ? g_hrow[hbase + tau + (m << 6)] : __float2half2_rn(0.f);

    // ---- prefetch image 0 ----
    __half2 traw[8];
#pragma unroll
    for (int m = 0; m < 8; m++)
        traw[m] = valid ? g_scratch[cbase + ((size_t)b0 << 9) + tau + (m << 6)]
                        : __float2half2_rn(0.f);

    // ---- fused per-image means: warp w reduces image b0+w ----
    {
        int w = threadIdx.x >> 5, l = threadIdx.x & 31;
        float v = g_parts[((b0 + w) << 6) + l] + g_parts[((b0 + w) << 6) + 32 + l];
#pragma unroll
        for (int o = 16; o; o >>= 1) v += __shfl_down_sync(0xffffffffu, v, o);
        if (l == 0) smean[w] = v * (1.0f / 262144.0f);
        __syncthreads();
    }

    int pbS = tau + (tau >> 3);
    int pbL = 72 * g + jj;

    float acc[8];
#pragma unroll
    for (int m = 0; m < 8; m++) acc[m] = 0.f;

    for (int bi = 0; bi < 8; bi++) {
        __half2 mh = __float2half2_rn(-smean[bi]);
        __half2* s = smbuf[bi & 1][f];

        // stage 0 (registers): HFMA2 correction + convert + dft8 + twiddle chain
        float2 tc[8];
#pragma unroll
        for (int m = 0; m < 8; m++) {
            __half2 th = __hfma2(mh, hvh[m], traw[m]);
            tc[m] = __half22float2(th);
        }
        dft8(tc);
        twiddle_chain(tc, w0);
#pragma unroll
        for (int q = 0; q < 8; q++)
            s[pbS + 72 * q] = __floats2half2_rn(tc[q].x, tc[q].y);

        // prefetch next image into dead traw
        if (bi < 7 && valid) {
            int b = b0 + bi + 1;
#pragma unroll
            for (int m = 0; m < 8; m++)
                traw[m] = g_scratch[cbase + ((size_t)b << 9) + tau + (m << 6)];
        }
        BARSYNC(bar);     // data-ready; WAR vs image bi-2 guaranteed by double buffer

        // stage 1 in registers
        float2 u[8];
#pragma unroll
        for (int m = 0; m < 8; m++) u[m] = __half22float2(s[pbL + 9 * m]);
        dft8(u);
        twiddle_chain(u, w1);

        // fp16 shuffle exchange + stage 2 + accumulate
        unsigned int uh[8];
#pragma unroll
        for (int q = 0; q < 8; q++) { HU h; h.h = __floats2half2_rn(u[q].x, u[q].y); uh[q] = h.u; }
        transpose8h(uh, jj);
#pragma unroll
        for (int m = 0; m < 8; m++) { HU h; h.u = uh[m]; u[m] = __half22float2(h.h); }
        dft8(u);
#pragma unroll
        for (int m = 0; m < 8; m++)
            acc[m] = fmaf(u[m].x, u[m].x, fmaf(u[m].y, u[m].y, acc[m]));
    }

    if (valid) {
        int rlo = (jj << 3) + g;
#pragma unroll
        for (int m = 0; m < 8; m++) {
            int r = (m << 6) + rlo;
            atomicAdd(&g_accum[r * NFREQ + c], acc[m]);
        }
    }
}

// ---------------- kernel 3: nps2D + radial binning — 2 rows/block, batched loads --------------
__global__ void __launch_bounds__(256) k_finalize2d(float* __restrict__ out) {
    __shared__ float ssum[NFREQ];
    __shared__ float scnt[NFREQ];
    int i0 = blockIdx.x << 1;
    int tid = threadIdx.x;
    if (tid < NFREQ) { ssum[tid] = 0.f; scnt[tid] = 0.f; }
    if (tid + 256 < NFREQ) { ssum[tid + 256] = 0.f; scnt[tid + 256] = 0.f; }
    __syncthreads();

    const float SC = (float)(0.01 / (262144.0 * 128.0));
    float vals[4];
#pragma unroll
    for (int h = 0; h < 4; h++) {                    // batch 4 independent gathers (MLP 4)
        int i = i0 + (h >> 1);
        int j = tid + ((h & 1) << 8);
        int u = i ^ 256, v = j ^ 256;
        if (v > 256) { u = (512 - u) & 511; v = 512 - v; }
        vals[h] = g_accum[u * NFREQ + v] * SC;
    }
#pragma unroll
    for (int h = 0; h < 4; h++) {
        int i = i0 + (h >> 1);
        int j = tid + ((h & 1) << 8);
        out[NFREQ + (i << 9) + j] = vals[h];
        int xi = i - 256, yj = j - 256;
        int rad = __float2int_rn(__fsqrt_rn((float)(xi * xi + yj * yj)));
        if (rad < NFREQ) {
            atomicAdd(&ssum[rad], vals[h]);
            atomicAdd(&scnt[rad], 1.0f);
        }
    }
    __syncthreads();

    int part = blockIdx.x & 31;
    if (tid < NFREQ && (ssum[tid] != 0.f || scnt[tid] != 0.f)) {
        atomicAdd(&g_psum[part][tid], ssum[tid]);
        atomicAdd(&g_pcnt[part][tid], scnt[tid]);
    }
    if (tid + 256 < NFREQ && (ssum[tid + 256] != 0.f || scnt[tid + 256] != 0.f)) {
        atomicAdd(&g_psum[part][tid + 256], ssum[tid + 256]);
        atomicAdd(&g_pcnt[part][tid + 256], scnt[tid + 256]);
    }
}

// ---------------- kernel 4: nps1D and f1D ----------------------------------------------------
__global__ void k_finalize1d(float* __restrict__ out) {
    int k = threadIdx.x;
    if (k < NFREQ) {
        float s = 0.f, c = 0.f;
#pragma unroll
        for (int p = 0; p < 32; p++) { s += g_psum[p][k]; c += g_pcnt[p][k]; }
        out[k] = s / c;
        out[NFREQ + N * N + k] = 5.0f * (float)k / 256.0f;
    }
}

extern "C" void kernel_launch(void* const* d_in, const int* in_sizes, int n_in,
                              void* d_out, int out_size) {
    const float* x = (const float*)d_in[0];
    float* out = (float*)d_out;

    k_init<<<1024, 256>>>();
    k_rowfft<<<2048 + 64, 256>>>(x);           // 4 images/block + 64 window blocks
    k_colfft<<<65 * 16, 256>>>();              // 4 cols x 8 images per block
    k_finalize2d<<<256, 256>>>(out);           // 2 rows per block
    k_finalize1d<<<1, NFREQ>>>(out);
}

// round 14
// speedup vs baseline: 1.7462x; 1.0505x over previous
#include <cuda_runtime.h>
#include <cuda_fp16.h>
#include <math.h>

#define N 512
#define NIMG 128
#define NFREQ 257
#define RS 65536                 // image scratch k-stride in half2 (=128*512)
#define GIMG 4                   // images per rowfft block

#define BARSYNC(id) asm volatile("bar.sync %0, 64;" :: "r"(id) : "memory")

// ---------------- device scratch ------------------------------------------------------------
static __device__ __half2 g_scratch[(size_t)NFREQ * RS];  // c-major: [k][b*512+r], ~67MB, fp16
static __device__ __half2 g_hrow[(size_t)NFREQ * N];      // rowFFT of hann, [k][r], 0.5MB
static __device__ float2  g_tw[N];                        // W_512^k
static __device__ __half2 g_hann2[256 * 512];             // hann pairs (row r, r+1), 0.5MB
static __device__ float   g_parts[NIMG * 64];
static __device__ float   g_hparts[64];
static __device__ float   g_accum[NFREQ * N];             // [c][r] — coalesced colfft reduction
static __device__ float   g_psum[32][NFREQ];
static __device__ float   g_pcnt[32][NFREQ];
static __device__ unsigned g_done;

__device__ __forceinline__ int adr2(int i) { return i + (i >> 3); }

// ---- packed helpers ---------------------------------------------------------------------
union F2U { float2 f; unsigned long long u; };
union HU  { __half2 h; unsigned int u; };
__device__ __forceinline__ float2 padd(float2 a, float2 b) {
    F2U A, B, C; A.f = a; B.f = b;
    asm("add.rn.f32x2 %0, %1, %2;" : "=l"(C.u) : "l"(A.u), "l"(B.u));
    return C.f;
}
__device__ __forceinline__ float2 psub(float2 a, float2 b) {
    F2U A, B, C; A.f = a; B.f = b;
    asm("fma.rn.f32x2 %0, %1, %2, %3;"
        : "=l"(C.u) : "l"(B.u), "l"(0xBF800000BF800000ULL), "l"(A.u));
    return C.f;
}
__device__ __forceinline__ float2 cmulf2(float2 a, float2 w) {
    return make_float2(a.x * w.x - a.y * w.y, a.x * w.y + a.y * w.x);
}

// ---- natural-order 8-point DFT --------------------------------------------------------------
__device__ __forceinline__ void dft8(float2* t) {
    float2 b0 = t[0], b1 = t[4], b2 = t[2], b3 = t[6];
    float2 b4 = t[1], b5 = t[5], b6 = t[3], b7 = t[7];
    float2 u0 = padd(b0, b1), u1 = psub(b0, b1), u2 = padd(b2, b3), u3 = psub(b2, b3);
    float2 u4 = padd(b4, b5), u5 = psub(b4, b5), u6 = padd(b6, b7), u7 = psub(b6, b7);
    float2 v0 = padd(u0, u2), v2 = psub(u0, u2);
    float2 v1 = make_float2(u1.x + u3.y, u1.y - u3.x);
    float2 v3 = make_float2(u1.x - u3.y, u1.y + u3.x);
    float2 v4 = padd(u4, u6), v6 = psub(u4, u6);
    float2 v5 = make_float2(u5.x + u7.y, u5.y - u7.x);
    float2 v7 = make_float2(u5.x - u7.y, u5.y + u7.x);
    const float C = 0.70710678118654752f;
    float2 a5 = make_float2(C * (v5.x + v5.y), C * (v5.y - v5.x));
    float2 a7 = make_float2(C * (v7.y - v7.x), -C * (v7.x + v7.y));
    t[0] = padd(v0, v4); t[4] = psub(v0, v4);
    t[1] = padd(v1, a5); t[5] = psub(v1, a5);
    t[2] = make_float2(v2.x + v6.y, v2.y - v6.x);
    t[6] = make_float2(v2.x - v6.y, v2.y + v6.x);
    t[3] = padd(v3, a7); t[7] = psub(v3, a7);
}

// ---- apply geometric twiddle chain: t[q] *= w^q, q=1..7 --------------------------------------
__device__ __forceinline__ void twiddle_chain(float2* t, float2 w) {
    float2 wq = w;
    t[1] = cmulf2(t[1], wq);
#pragma unroll
    for (int q = 2; q < 8; q++) {
        wq = cmulf2(wq, w);
        t[q] = cmulf2(t[q], wq);
    }
}

// ---- 8x8 half2 transpose across 8 lanes (SHFL.32, 3 rounds) ---------------------------------
__device__ __forceinline__ void transpose8h(unsigned int* u, int jj) {
#pragma unroll
    for (int k = 0; k < 3; k++) {
        const int m = 1 << k;
        bool hi = (jj & m) != 0;
#pragma unroll
        for (int i0 = 0; i0 < 8; i0++) {
            if ((i0 & m) == 0) {
                int i1 = i0 | m;
                unsigned int snd = hi ? u[i0] : u[i1];
                unsigned int rcv = __shfl_xor_sync(0xffffffffu, snd, m);
                if (hi) u[i0] = rcv; else u[i1] = rcv;
            }
        }
    }
}

// ---------------- kernel 0: init (twiddles, hann pairs, zero accumulators) -------------------
__global__ void k_init() {
    int p = blockIdx.x * blockDim.x + threadIdx.x;   // 0..262143
    if (p < 256 * 512) {
        int rp = p >> 9, j = p & 511;
        const float STEP = 512.0f / 511.0f;
        float lc = fmaf((float)j, STEP, -256.0f);
        float h0, h1;
        {
            float lr = fmaf((float)(2 * rp), STEP, -256.0f);
            float rd = sqrtf(lc * lc + lr * lr);
            h0 = (rd > 256.0f) ? 0.0f : 0.5f * (1.0f + cospif(rd * (1.0f / 256.0f)));
        }
        {
            float lr = fmaf((float)(2 * rp + 1), STEP, -256.0f);
            float rd = sqrtf(lc * lc + lr * lr);
            h1 = (rd > 256.0f) ? 0.0f : 0.5f * (1.0f + cospif(rd * (1.0f / 256.0f)));
        }
        g_hann2[p] = __floats2half2_rn(h0, h1);
    }
    if (p < NFREQ * N) g_accum[p] = 0.f;
    if (p < N) {
        double ang = -6.283185307179586476925286766559 * (double)p / 512.0;
        g_tw[p] = make_float2((float)cos(ang), (float)sin(ang));
    }
    if (p < 32 * NFREQ) { ((float*)g_psum)[p] = 0.f; ((float*)g_pcnt)[p] = 0.f; }
    if (p == 0) g_done = 0u;
}

// ---------------- kernel 1: DIF row FFTs, GIMG images per block (window blocks: 1) ------------
__global__ void __launch_bounds__(256) k_rowfft(const float* __restrict__ src) {
    __shared__ __half2 smA[4][576];
    __shared__ __half2 smB[4][576];
    __shared__ float red[8];
    bool win = blockIdx.x >= 2048;
    int rgrp = win ? (int)blockIdx.x - 2048 : (int)blockIdx.x & 63;
    int igrp = win ? 0 : (int)blockIdx.x >> 6;
    int r0   = rgrp << 3;
    __half2* dst = win ? g_hrow : g_scratch;
    int kstride  = win ? N : RS;
    int niter    = win ? 1 : GIMG;

    int tid = threadIdx.x;
    int f   = tid >> 6, tau = tid & 63;
    int g   = tau >> 3, jj = tau & 7;
    int rowA = r0 + 2 * f;
    const __half2* hP = g_hann2 + ((rowA >> 1) << 9);
    __half2* sA = smA[f];
    __half2* sB = smB[f];
    float2 w0 = g_tw[tau];
    float2 w1 = g_tw[jj << 3];
    int pbS = tau + (tau >> 3);
    int pbL = 72 * g + jj;

    __half2 hreg[8];
#pragma unroll
    for (int m = 0; m < 8; m++) hreg[m] = hP[tau + (m << 6)];

    for (int it = 0; it < niter; it++) {
        int b = (igrp << 2) + it;
        size_t srcbase = ((size_t)b << 18) + ((size_t)rowA << 9);

        // ---- load + stage 0 (stride 64) in registers ----
        float2 t[8];
        float lsum = 0.f;
#pragma unroll
        for (int m = 0; m < 8; m++) {
            int c = tau + (m << 6);
            float2 h2 = __half22float2(hreg[m]);
            float va = 1.0f, vb = 1.0f;
            if (!win) {
                va = src[srcbase + c];
                vb = src[srcbase + 512 + c];
                lsum += va + vb;
            }
            t[m] = make_float2(va * h2.x, vb * h2.y);
        }
        dft8(t);
        twiddle_chain(t, w0);
#pragma unroll
        for (int q = 0; q < 8; q++) sA[pbS + 72 * q] = __floats2half2_rn(t[q].x, t[q].y);

#pragma unroll
        for (int o = 16; o; o >>= 1) lsum += __shfl_down_sync(0xffffffffu, lsum, o);
        __syncthreads();                        // sync1: smA ready; prev red consumed
        if ((tid & 31) == 0) red[tid >> 5] = lsum;

        // ---- stage 1 (stride 8) in registers ----
        float2 u[8];
#pragma unroll
        for (int m = 0; m < 8; m++) u[m] = __half22float2(sA[pbL + 9 * m]);
        dft8(u);
        twiddle_chain(u, w1);

        // ---- fp16 shuffle exchange + stage 2 ----
        unsigned int uh[8];
#pragma unroll
        for (int q = 0; q < 8; q++) { HU h; h.h = __floats2half2_rn(u[q].x, u[q].y); uh[q] = h.u; }
        transpose8h(uh, jj);
#pragma unroll
        for (int m = 0; m < 8; m++) { HU h; h.u = uh[m]; u[m] = __half22float2(h.h); }
        dft8(u);

#pragma unroll
        for (int m = 0; m < 8; m++)
            sB[adr2((m << 6) + (jj << 3) + g)] = __floats2half2_rn(u[m].x, u[m].y);
        __syncthreads();                        // sync2: smB + red ready

        if (tid == 0) {
            float tot = 0.f;
#pragma unroll
            for (int p = 0; p < 8; p++) tot += red[p];
            if (win) g_hparts[rgrp] = tot;
            else     g_parts[(b << 6) + rgrp] = tot;
        }

        // ---- Hermitian unpack: one thread per (pair,k) writes both rows as one STG.64 ----
        int p      = tid & 3;
        int kslot  = tid >> 2;
        __half2* so = smB[p];
        size_t dbase = ((size_t)b << 9) + r0 + 2 * p;
        if (win) dbase = r0 + 2 * p;
#pragma unroll
        for (int kk = 0; kk < 5; kk++) {
            int k = kslot + (kk << 6);
            if (k < NFREQ) {
                float2 z = __half22float2(so[adr2(k)]);
                float2 y = __half22float2(so[adr2((512 - k) & 511)]);
                __half2 A = __floats2half2_rn(0.5f * (z.x + y.x), 0.5f * (z.y - y.y));
                __half2 B = __floats2half2_rn(0.5f * (z.y + y.y), 0.5f * (y.x - z.x));
                F2U pack; ((__half2*)&pack.u)[0] = A; ((__half2*)&pack.u)[1] = B;
                *reinterpret_cast<unsigned long long*>(
                    &dst[(size_t)k * kstride + dbase]) = pack.u;
            }
        }
    }
}

// ---------------- kernel 2: DIF column FFTs — coalesced [c][r] reduction ----------------------
__global__ void __launch_bounds__(256, 4) k_colfft() {
    __shared__ __half2 smbuf[2][4][576];
    __shared__ float smean[8];
    int ct  = blockIdx.x % 65;
    int grp = blockIdx.x / 65;             // 0..15 : 8 images each
    int f   = threadIdx.x >> 6;
    int tau = threadIdx.x & 63;
    int g   = tau >> 3, jj = tau & 7;
    int c   = (ct << 2) + f;
    bool valid = (c < NFREQ);
    size_t cbase = valid ? (size_t)c * RS : 0;
    int b0 = grp << 3;
    int bar = f + 1;
    float2 w0 = g_tw[tau];
    float2 w1 = g_tw[jj << 3];

    __half2 hvh[8];
    size_t hbase = valid ? ((size_t)c << 9) : 0;
#pragma unroll
    for (int m = 0; m < 8; m++)
        hvh[m] = valid ? g_hrow[hbase + tau + (m << 6)] : __float2half2_rn(0.f);

    __half2 traw[8];
#pragma unroll
    for (int m = 0; m < 8; m++)
        traw[m] = valid ? g_scratch[cbase + ((size_t)b0 << 9) + tau + (m << 6)]
                        : __float2half2_rn(0.f);

    {
        int w = threadIdx.x >> 5, l = threadIdx.x & 31;
        float v = g_parts[((b0 + w) << 6) + l] + g_parts[((b0 + w) << 6) + 32 + l];
#pragma unroll
        for (int o = 16; o; o >>= 1) v += __shfl_down_sync(0xffffffffu, v, o);
        if (l == 0) smean[w] = v * (1.0f / 262144.0f);
        __syncthreads();
    }

    int pbS = tau + (tau >> 3);
    int pbL = 72 * g + jj;

    float acc[8];
#pragma unroll
    for (int m = 0; m < 8; m++) acc[m] = 0.f;

    for (int bi = 0; bi < 8; bi++) {
        __half2 mh = __float2half2_rn(-smean[bi]);
        __half2* s = smbuf[bi & 1][f];

        float2 tc[8];
#pragma unroll
        for (int m = 0; m < 8; m++) {
            __half2 th = __hfma2(mh, hvh[m], traw[m]);
            tc[m] = __half22float2(th);
        }
        dft8(tc);
        twiddle_chain(tc, w0);
#pragma unroll
        for (int q = 0; q < 8; q++)
            s[pbS + 72 * q] = __floats2half2_rn(tc[q].x, tc[q].y);

        if (bi < 7 && valid) {
            int b = b0 + bi + 1;
#pragma unroll
            for (int m = 0; m < 8; m++)
                traw[m] = g_scratch[cbase + ((size_t)b << 9) + tau + (m << 6)];
        }
        BARSYNC(bar);

        float2 u[8];
#pragma unroll
        for (int m = 0; m < 8; m++) u[m] = __half22float2(s[pbL + 9 * m]);
        dft8(u);
        twiddle_chain(u, w1);

        unsigned int uh[8];
#pragma unroll
        for (int q = 0; q < 8; q++) { HU h; h.h = __floats2half2_rn(u[q].x, u[q].y); uh[q] = h.u; }
        transpose8h(uh, jj);
#pragma unroll
        for (int m = 0; m < 8; m++) { HU h; h.u = uh[m]; u[m] = __half22float2(h.h); }
        dft8(u);
#pragma unroll
        for (int m = 0; m < 8; m++)
            acc[m] = fmaf(u[m].x, u[m].x, fmaf(u[m].y, u[m].y, acc[m]));
    }

    if (valid) {
        int rlo = (jj << 3) + g;
#pragma unroll
        for (int m = 0; m < 8; m++) {
            int r = (m << 6) + rlo;
            atomicAdd(&g_accum[c * N + r], acc[m]);   // [c][r]: warp lands in 2 lines
        }
    }
}

// ---------------- kernel 3: nps2D + radial binning + fused 1D tail ----------------------------
// 512 blocks (one output row i each); last-done block computes nps1D and f1D.
__global__ void __launch_bounds__(256) k_finalize2d(float* __restrict__ out) {
    __shared__ float ssum[NFREQ];
    __shared__ float scnt[NFREQ];
    int i = blockIdx.x;
    int tid = threadIdx.x;
    if (tid < NFREQ) { ssum[tid] = 0.f; scnt[tid] = 0.f; }
    if (tid + 256 < NFREQ) { ssum[tid + 256] = 0.f; scnt[tid + 256] = 0.f; }
    __syncthreads();

    const float SC = (float)(0.01 / (262144.0 * 128.0));
    int xi = i - 256;
    float vals[2];
#pragma unroll
    for (int h = 0; h < 2; h++) {                    // batch both gathers (MLP 2)
        int j = tid + (h << 8);
        int u = i ^ 256, v = j ^ 256;
        if (v > 256) { u = (512 - u) & 511; v = 512 - v; }
        vals[h] = g_accum[v * N + u] * SC;
    }
#pragma unroll
    for (int h = 0; h < 2; h++) {
        int j = tid + (h << 8);
        out[NFREQ + (i << 9) + j] = vals[h];
        int yj = j - 256;
        int rad = __float2int_rn(__fsqrt_rn((float)(xi * xi + yj * yj)));
        if (rad < NFREQ) {
            atomicAdd(&ssum[rad], vals[h]);
            atomicAdd(&scnt[rad], 1.0f);
        }
    }
    __syncthreads();

    int part = i & 31;
    if (tid < NFREQ && (ssum[tid] != 0.f || scnt[tid] != 0.f)) {
        atomicAdd(&g_psum[part][tid], ssum[tid]);
        atomicAdd(&g_pcnt[part][tid], scnt[tid]);
    }
    if (tid + 256 < NFREQ && (ssum[tid + 256] != 0.f || scnt[tid + 256] != 0.f)) {
        atomicAdd(&g_psum[part][tid + 256], ssum[tid + 256]);
        atomicAdd(&g_pcnt[part][tid + 256], scnt[tid + 256]);
    }

    // ---- fused 1D tail: last block to finish sums the partials ----
    __threadfence();
    __shared__ unsigned slast;
    __syncthreads();
    if (tid == 0) slast = atomicAdd(&g_done, 1u);
    __syncthreads();
    if (slast == (unsigned)(gridDim.x - 1)) {
        __threadfence();          // acquire: see all blocks' psum/pcnt
#pragma unroll
        for (int h = 0; h < 2; h++) {
            int k = tid + (h << 8);
            if (k < NFREQ) {
                float s = 0.f, cth = 0.f;
#pragma unroll
                for (int p = 0; p < 32; p++) { s += g_psum[p][k]; cth += g_pcnt[p][k]; }
                out[k] = s / cth;
                out[NFREQ + N * N + k] = 5.0f * (float)k / 256.0f;
            }
        }
    }
}

extern "C" void kernel_launch(void* const* d_in, const int* in_sizes, int n_in,
                              void* d_out, int out_size) {
    const float* x = (const float*)d_in[0];
    float* out = (float*)d_out;

    k_init<<<1024, 256>>>();
    k_rowfft<<<2048 + 64, 256>>>(x);           // 4 images/block + 64 window blocks
    k_colfft<<<65 * 16, 256>>>();              // 4 cols x 8 images per block
    k_finalize2d<<<N, 256>>>(out);             // includes fused 1D tail
}

// round 15
// speedup vs baseline: 1.7649x; 1.0107x over previous
#include <cuda_runtime.h>
#include <cuda_fp16.h>
#include <math.h>

#define N 512
#define NIMG 128
#define NFREQ 257
#define RS 65536                 // image scratch k-stride in half2 (=128*512)
#define GIMG 4                   // images per rowfft block

#define BARSYNC(id) asm volatile("bar.sync %0, 64;" :: "r"(id) : "memory")

// ---------------- device scratch ------------------------------------------------------------
static __device__ __half2 g_scratch[(size_t)NFREQ * RS];  // c-major: [k][b*512+r], ~67MB, fp16
static __device__ __half2 g_hrow[(size_t)NFREQ * N];      // rowFFT of hann, [k][r], 0.5MB
static __device__ float2  g_tw[N];                        // W_512^k
static __device__ __half2 g_hann2[256 * 512];             // hann pairs (row r, r+1), 0.5MB
static __device__ float   g_parts[NIMG * 64];
static __device__ float   g_hparts[64];
static __device__ float   g_accum[NFREQ * N];             // [c][r] — coalesced colfft reduction
static __device__ float   g_psum[32][NFREQ];
static __device__ float   g_pcnt[32][NFREQ];
static __device__ unsigned g_done;

__device__ __forceinline__ int adr2(int i) { return i + (i >> 3); }

// ---- packed helpers ---------------------------------------------------------------------
union F2U { float2 f; unsigned long long u; };
union HU  { __half2 h; unsigned int u; };
__device__ __forceinline__ float2 padd(float2 a, float2 b) {
    F2U A, B, C; A.f = a; B.f = b;
    asm("add.rn.f32x2 %0, %1, %2;" : "=l"(C.u) : "l"(A.u), "l"(B.u));
    return C.f;
}
__device__ __forceinline__ float2 psub(float2 a, float2 b) {
    F2U A, B, C; A.f = a; B.f = b;
    asm("fma.rn.f32x2 %0, %1, %2, %3;"
        : "=l"(C.u) : "l"(B.u), "l"(0xBF800000BF800000ULL), "l"(A.u));
    return C.f;
}
__device__ __forceinline__ float2 cmulf2(float2 a, float2 w) {
    return make_float2(a.x * w.x - a.y * w.y, a.x * w.y + a.y * w.x);
}

// ---- natural-order 8-point DFT --------------------------------------------------------------
__device__ __forceinline__ void dft8(float2* t) {
    float2 b0 = t[0], b1 = t[4], b2 = t[2], b3 = t[6];
    float2 b4 = t[1], b5 = t[5], b6 = t[3], b7 = t[7];
    float2 u0 = padd(b0, b1), u1 = psub(b0, b1), u2 = padd(b2, b3), u3 = psub(b2, b3);
    float2 u4 = padd(b4, b5), u5 = psub(b4, b5), u6 = padd(b6, b7), u7 = psub(b6, b7);
    float2 v0 = padd(u0, u2), v2 = psub(u0, u2);
    float2 v1 = make_float2(u1.x + u3.y, u1.y - u3.x);
    float2 v3 = make_float2(u1.x - u3.y, u1.y + u3.x);
    float2 v4 = padd(u4, u6), v6 = psub(u4, u6);
    float2 v5 = make_float2(u5.x + u7.y, u5.y - u7.x);
    float2 v7 = make_float2(u5.x - u7.y, u5.y + u7.x);
    const float C = 0.70710678118654752f;
    float2 a5 = make_float2(C * (v5.x + v5.y), C * (v5.y - v5.x));
    float2 a7 = make_float2(C * (v7.y - v7.x), -C * (v7.x + v7.y));
    t[0] = padd(v0, v4); t[4] = psub(v0, v4);
    t[1] = padd(v1, a5); t[5] = psub(v1, a5);
    t[2] = make_float2(v2.x + v6.y, v2.y - v6.x);
    t[6] = make_float2(v2.x - v6.y, v2.y + v6.x);
    t[3] = padd(v3, a7); t[7] = psub(v3, a7);
}

// ---- apply geometric twiddle chain: t[q] *= w^q, q=1..7 --------------------------------------
__device__ __forceinline__ void twiddle_chain(float2* t, float2 w) {
    float2 wq = w;
    t[1] = cmulf2(t[1], wq);
#pragma unroll
    for (int q = 2; q < 8; q++) {
        wq = cmulf2(wq, w);
        t[q] = cmulf2(t[q], wq);
    }
}

// ---- 8x8 half2 transpose across 8 lanes (SHFL.32, 3 rounds) ---------------------------------
__device__ __forceinline__ void transpose8h(unsigned int* u, int jj) {
#pragma unroll
    for (int k = 0; k < 3; k++) {
        const int m = 1 << k;
        bool hi = (jj & m) != 0;
#pragma unroll
        for (int i0 = 0; i0 < 8; i0++) {
            if ((i0 & m) == 0) {
                int i1 = i0 | m;
                unsigned int snd = hi ? u[i0] : u[i1];
                unsigned int rcv = __shfl_xor_sync(0xffffffffu, snd, m);
                if (hi) u[i0] = rcv; else u[i1] = rcv;
            }
        }
    }
}

// ---------------- kernel 0: init (twiddles, hann pairs, zero accumulators) -------------------
__global__ void k_init() {
    int p = blockIdx.x * blockDim.x + threadIdx.x;   // 0..262143
    if (p < 256 * 512) {
        int rp = p >> 9, j = p & 511;
        const float STEP = 512.0f / 511.0f;
        float lc = fmaf((float)j, STEP, -256.0f);
        float h0, h1;
        {
            float lr = fmaf((float)(2 * rp), STEP, -256.0f);
            float rd = sqrtf(lc * lc + lr * lr);
            h0 = (rd > 256.0f) ? 0.0f : 0.5f * (1.0f + cospif(rd * (1.0f / 256.0f)));
        }
        {
            float lr = fmaf((float)(2 * rp + 1), STEP, -256.0f);
            float rd = sqrtf(lc * lc + lr * lr);
            h1 = (rd > 256.0f) ? 0.0f : 0.5f * (1.0f + cospif(rd * (1.0f / 256.0f)));
        }
        g_hann2[p] = __floats2half2_rn(h0, h1);
    }
    if (p < NFREQ * N) g_accum[p] = 0.f;
    if (p < N) {
        double ang = -6.283185307179586476925286766559 * (double)p / 512.0;
        g_tw[p] = make_float2((float)cos(ang), (float)sin(ang));
    }
    if (p < 32 * NFREQ) { ((float*)g_psum)[p] = 0.f; ((float*)g_pcnt)[p] = 0.f; }
    if (p == 0) g_done = 0u;
}

// ---------------- kernel 1: DIF row FFTs, GIMG images per block (window blocks: 1) ------------
__global__ void __launch_bounds__(256) k_rowfft(const float* __restrict__ src) {
    __shared__ __half2 smA[4][576];
    __shared__ __half2 smB[4][576];
    __shared__ float red[8];
    bool win = blockIdx.x >= 2048;
    int rgrp = win ? (int)blockIdx.x - 2048 : (int)blockIdx.x & 63;
    int igrp = win ? 0 : (int)blockIdx.x >> 6;
    int r0   = rgrp << 3;
    __half2* dst = win ? g_hrow : g_scratch;
    int kstride  = win ? N : RS;
    int niter    = win ? 1 : GIMG;

    int tid = threadIdx.x;
    int f   = tid >> 6, tau = tid & 63;
    int g   = tau >> 3, jj = tau & 7;
    int rowA = r0 + 2 * f;
    const __half2* hP = g_hann2 + ((rowA >> 1) << 9);
    __half2* sA = smA[f];
    __half2* sB = smB[f];
    float2 w0 = g_tw[tau];
    float2 w1 = g_tw[jj << 3];
    int pbS = tau + (tau >> 3);
    int pbL = 72 * g + jj;

    __half2 hreg[8];
#pragma unroll
    for (int m = 0; m < 8; m++) hreg[m] = hP[tau + (m << 6)];

    for (int it = 0; it < niter; it++) {
        int b = (igrp << 2) + it;
        size_t srcbase = ((size_t)b << 18) + ((size_t)rowA << 9);

        // ---- load + stage 0 (stride 64) in registers ----
        float2 t[8];
        float lsum = 0.f;
#pragma unroll
        for (int m = 0; m < 8; m++) {
            int c = tau + (m << 6);
            float2 h2 = __half22float2(hreg[m]);
            float va = 1.0f, vb = 1.0f;
            if (!win) {
                va = src[srcbase + c];
                vb = src[srcbase + 512 + c];
                lsum += va + vb;
            }
            t[m] = make_float2(va * h2.x, vb * h2.y);
        }
        dft8(t);
        twiddle_chain(t, w0);
#pragma unroll
        for (int q = 0; q < 8; q++) sA[pbS + 72 * q] = __floats2half2_rn(t[q].x, t[q].y);

#pragma unroll
        for (int o = 16; o; o >>= 1) lsum += __shfl_down_sync(0xffffffffu, lsum, o);
        __syncthreads();                        // sync1: smA ready; prev red consumed
        if ((tid & 31) == 0) red[tid >> 5] = lsum;

        // ---- stage 1 (stride 8) in registers ----
        float2 u[8];
#pragma unroll
        for (int m = 0; m < 8; m++) u[m] = __half22float2(sA[pbL + 9 * m]);
        dft8(u);
        twiddle_chain(u, w1);

        // ---- fp16 shuffle exchange + stage 2 ----
        unsigned int uh[8];
#pragma unroll
        for (int q = 0; q < 8; q++) { HU h; h.h = __floats2half2_rn(u[q].x, u[q].y); uh[q] = h.u; }
        transpose8h(uh, jj);
#pragma unroll
        for (int m = 0; m < 8; m++) { HU h; h.u = uh[m]; u[m] = __half22float2(h.h); }
        dft8(u);

#pragma unroll
        for (int m = 0; m < 8; m++)
            sB[adr2((m << 6) + (jj << 3) + g)] = __floats2half2_rn(u[m].x, u[m].y);
        __syncthreads();                        // sync2: smB + red ready

        if (tid == 0) {
            float tot = 0.f;
#pragma unroll
            for (int p = 0; p < 8; p++) tot += red[p];
            if (win) g_hparts[rgrp] = tot;
            else     g_parts[(b << 6) + rgrp] = tot;
        }

        // ---- Hermitian unpack: one thread per (pair,k) writes both rows as one STG.64 ----
        int p      = tid & 3;
        int kslot  = tid >> 2;
        __half2* so = smB[p];
        size_t dbase = ((size_t)b << 9) + r0 + 2 * p;
        if (win) dbase = r0 + 2 * p;
#pragma unroll
        for (int kk = 0; kk < 5; kk++) {
            int k = kslot + (kk << 6);
            if (k < NFREQ) {
                float2 z = __half22float2(so[adr2(k)]);
                float2 y = __half22float2(so[adr2((512 - k) & 511)]);
                __half2 A = __floats2half2_rn(0.5f * (z.x + y.x), 0.5f * (z.y - y.y));
                __half2 B = __floats2half2_rn(0.5f * (z.y + y.y), 0.5f * (y.x - z.x));
                F2U pack; ((__half2*)&pack.u)[0] = A; ((__half2*)&pack.u)[1] = B;
                *reinterpret_cast<unsigned long long*>(
                    &dst[(size_t)k * kstride + dbase]) = pack.u;
            }
        }
    }
}

// ---------------- kernel 2: DIF column FFTs — coalesced [c][r] reduction ----------------------
__global__ void __launch_bounds__(256, 4) k_colfft() {
    __shared__ __half2 smbuf[2][4][576];
    __shared__ float smean[8];
    int ct  = blockIdx.x % 65;
    int grp = blockIdx.x / 65;             // 0..15 : 8 images each
    int f   = threadIdx.x >> 6;
    int tau = threadIdx.x & 63;
    int g   = tau >> 3, jj = tau & 7;
    int c   = (ct << 2) + f;
    bool valid = (c < NFREQ);
    size_t cbase = valid ? (size_t)c * RS : 0;
    int b0 = grp << 3;
    int bar = f + 1;
    float2 w0 = g_tw[tau];
    float2 w1 = g_tw[jj << 3];

    __half2 hvh[8];
    size_t hbase = valid ? ((size_t)c << 9) : 0;
#pragma unroll
    for (int m = 0; m < 8; m++)
        hvh[m] = valid ? g_hrow[hbase + tau + (m << 6)] : __float2half2_rn(0.f);

    __half2 traw[8];
#pragma unroll
    for (int m = 0; m < 8; m++)
        traw[m] = valid ? g_scratch[cbase + ((size_t)b0 << 9) + tau + (m << 6)]
                        : __float2half2_rn(0.f);

    {
        int w = threadIdx.x >> 5, l = threadIdx.x & 31;
        float v = g_parts[((b0 + w) << 6) + l] + g_parts[((b0 + w) << 6) + 32 + l];
#pragma unroll
        for (int o = 16; o; o >>= 1) v += __shfl_down_sync(0xffffffffu, v, o);
        if (l == 0) smean[w] = v * (1.0f / 262144.0f);
        __syncthreads();
    }

    int pbS = tau + (tau >> 3);
    int pbL = 72 * g + jj;

    float acc[8];
#pragma unroll
    for (int m = 0; m < 8; m++) acc[m] = 0.f;

    for (int bi = 0; bi < 8; bi++) {
        __half2 mh = __float2half2_rn(-smean[bi]);
        __half2* s = smbuf[bi & 1][f];

        float2 tc[8];
#pragma unroll
        for (int m = 0; m < 8; m++) {
            __half2 th = __hfma2(mh, hvh[m], traw[m]);
            tc[m] = __half22float2(th);
        }
        dft8(tc);
        twiddle_chain(tc, w0);
#pragma unroll
        for (int q = 0; q < 8; q++)
            s[pbS + 72 * q] = __floats2half2_rn(tc[q].x, tc[q].y);

        if (bi < 7 && valid) {
            int b = b0 + bi + 1;
#pragma unroll
            for (int m = 0; m < 8; m++)
                traw[m] = g_scratch[cbase + ((size_t)b << 9) + tau + (m << 6)];
        }
        BARSYNC(bar);

        float2 u[8];
#pragma unroll
        for (int m = 0; m < 8; m++) u[m] = __half22float2(s[pbL + 9 * m]);
        dft8(u);
        twiddle_chain(u, w1);

        unsigned int uh[8];
#pragma unroll
        for (int q = 0; q < 8; q++) { HU h; h.h = __floats2half2_rn(u[q].x, u[q].y); uh[q] = h.u; }
        transpose8h(uh, jj);
#pragma unroll
        for (int m = 0; m < 8; m++) { HU h; h.u = uh[m]; u[m] = __half22float2(h.h); }
        dft8(u);
#pragma unroll
        for (int m = 0; m < 8; m++)
            acc[m] = fmaf(u[m].x, u[m].x, fmaf(u[m].y, u[m].y, acc[m]));
    }

    if (valid) {
        int rlo = (jj << 3) + g;
#pragma unroll
        for (int m = 0; m < 8; m++) {
            int r = (m << 6) + rlo;
            atomicAdd(&g_accum[c * N + r], acc[m]);   // [c][r]: warp lands in 2 lines
        }
    }
}

// ---------------- kernel 3: nps2D + radial binning + fused 1D tail ----------------------------
// block = output COLUMN j (mirror test uniform per block; accum reads coalesced);
// thread = output row i (2 rows per thread). Last-done block computes nps1D/f1D.
__global__ void __launch_bounds__(256) k_finalize2d(float* __restrict__ out) {
    __shared__ float ssum[NFREQ];
    __shared__ float scnt[NFREQ];
    int j = blockIdx.x;
    int tid = threadIdx.x;
    if (tid < NFREQ) { ssum[tid] = 0.f; scnt[tid] = 0.f; }
    if (tid + 256 < NFREQ) { ssum[tid + 256] = 0.f; scnt[tid + 256] = 0.f; }
    __syncthreads();

    const float SC = (float)(0.01 / (262144.0 * 128.0));
    int v = j ^ 256;
    bool mir = v > 256;
    if (mir) v = 512 - v;
    const float* arow = g_accum + (size_t)v * N;   // coalesced row
    int yj = j - 256;
    int yj2 = yj * yj;

    float vals[2];
#pragma unroll
    for (int h = 0; h < 2; h++) {
        int i = tid + (h << 8);
        int u = i ^ 256;
        if (mir) u = (512 - u) & 511;
        vals[h] = arow[u] * SC;
    }
#pragma unroll
    for (int h = 0; h < 2; h++) {
        int i = tid + (h << 8);
        out[NFREQ + (i << 9) + j] = vals[h];       // scattered store: fire-and-forget
        int xi = i - 256;
        int rad = __float2int_rn(__fsqrt_rn((float)(xi * xi + yj2)));
        if (rad < NFREQ) {
            atomicAdd(&ssum[rad], vals[h]);
            atomicAdd(&scnt[rad], 1.0f);
        }
    }
    __syncthreads();

    int part = j & 31;
    if (tid < NFREQ && (ssum[tid] != 0.f || scnt[tid] != 0.f)) {
        atomicAdd(&g_psum[part][tid], ssum[tid]);
        atomicAdd(&g_pcnt[part][tid], scnt[tid]);
    }
    if (tid + 256 < NFREQ && (ssum[tid + 256] != 0.f || scnt[tid + 256] != 0.f)) {
        atomicAdd(&g_psum[part][tid + 256], ssum[tid + 256]);
        atomicAdd(&g_pcnt[part][tid + 256], scnt[tid + 256]);
    }

    // ---- fused 1D tail: last block to finish sums the partials ----
    __threadfence();
    __shared__ unsigned slast;
    __syncthreads();
    if (tid == 0) slast = atomicAdd(&g_done, 1u);
    __syncthreads();
    if (slast == (unsigned)(gridDim.x - 1)) {
        __threadfence();          // acquire: see all blocks' psum/pcnt
#pragma unroll
        for (int h = 0; h < 2; h++) {
            int k = tid + (h << 8);
            if (k < NFREQ) {
                float s = 0.f, cth = 0.f;
#pragma unroll
                for (int p = 0; p < 32; p++) { s += g_psum[p][k]; cth += g_pcnt[p][k]; }
                out[k] = s / cth;
                out[NFREQ + N * N + k] = 5.0f * (float)k / 256.0f;
            }
        }
    }
}

extern "C" void kernel_launch(void* const* d_in, const int* in_sizes, int n_in,
                              void* d_out, int out_size) {
    const float* x = (const float*)d_in[0];
    float* out = (float*)d_out;

    k_init<<<1024, 256>>>();
    k_rowfft<<<2048 + 64, 256>>>(x);           // 4 images/block + 64 window blocks
    k_colfft<<<65 * 16, 256>>>();              // 4 cols x 8 images per block
    k_finalize2d<<<N, 256>>>(out);             // column-blocks + fused 1D tail
}

// round 16
// speedup vs baseline: 1.7700x; 1.0029x over previous
#include <cuda_runtime.h>
#include <cuda_fp16.h>
#include <math.h>

#define N 512
#define NIMG 128
#define NFREQ 257
#define RS 65536                 // image scratch k-stride in half2 (=128*512)
#define GIMG 4                   // images per rowfft block

#define BARSYNC(id) asm volatile("bar.sync %0, 64;" :: "r"(id) : "memory")

// ---------------- device scratch ------------------------------------------------------------
static __device__ __half2 g_scratch[(size_t)NFREQ * RS];  // c-major: [k][b*512+r], ~67MB, fp16
static __device__ __half2 g_hrow[(size_t)NFREQ * N];      // rowFFT of hann, [k][r], 0.5MB
static __device__ float2  g_tw[N];                        // W_512^k
static __device__ __half2 g_hann2[256 * 512];             // hann pairs (row r, r+1), 0.5MB
static __device__ float   g_parts[NIMG * 64];
static __device__ float   g_hparts[64];
static __device__ float   g_accum[NFREQ * N];             // [c][r] — coalesced colfft reduction
static __device__ float   g_psum[32][NFREQ];
static __device__ float   g_pcnt[32][NFREQ];
static __device__ unsigned g_done;

__device__ __forceinline__ int adr2(int i) { return i + (i >> 3); }

// ---- packed helpers ---------------------------------------------------------------------
union F2U { float2 f; unsigned long long u; };
union HU  { __half2 h; unsigned int u; };
__device__ __forceinline__ float2 padd(float2 a, float2 b) {
    F2U A, B, C; A.f = a; B.f = b;
    asm("add.rn.f32x2 %0, %1, %2;" : "=l"(C.u) : "l"(A.u), "l"(B.u));
    return C.f;
}
__device__ __forceinline__ float2 psub(float2 a, float2 b) {
    F2U A, B, C; A.f = a; B.f = b;
    asm("fma.rn.f32x2 %0, %1, %2, %3;"
        : "=l"(C.u) : "l"(B.u), "l"(0xBF800000BF800000ULL), "l"(A.u));
    return C.f;
}
__device__ __forceinline__ float2 cmulf2(float2 a, float2 w) {
    return make_float2(a.x * w.x - a.y * w.y, a.x * w.y + a.y * w.x);
}

// ---- natural-order 8-point DFT --------------------------------------------------------------
__device__ __forceinline__ void dft8(float2* t) {
    float2 b0 = t[0], b1 = t[4], b2 = t[2], b3 = t[6];
    float2 b4 = t[1], b5 = t[5], b6 = t[3], b7 = t[7];
    float2 u0 = padd(b0, b1), u1 = psub(b0, b1), u2 = padd(b2, b3), u3 = psub(b2, b3);
    float2 u4 = padd(b4, b5), u5 = psub(b4, b5), u6 = padd(b6, b7), u7 = psub(b6, b7);
    float2 v0 = padd(u0, u2), v2 = psub(u0, u2);
    float2 v1 = make_float2(u1.x + u3.y, u1.y - u3.x);
    float2 v3 = make_float2(u1.x - u3.y, u1.y + u3.x);
    float2 v4 = padd(u4, u6), v6 = psub(u4, u6);
    float2 v5 = make_float2(u5.x + u7.y, u5.y - u7.x);
    float2 v7 = make_float2(u5.x - u7.y, u5.y + u7.x);
    const float C = 0.70710678118654752f;
    float2 a5 = make_float2(C * (v5.x + v5.y), C * (v5.y - v5.x));
    float2 a7 = make_float2(C * (v7.y - v7.x), -C * (v7.x + v7.y));
    t[0] = padd(v0, v4); t[4] = psub(v0, v4);
    t[1] = padd(v1, a5); t[5] = psub(v1, a5);
    t[2] = make_float2(v2.x + v6.y, v2.y - v6.x);
    t[6] = make_float2(v2.x - v6.y, v2.y + v6.x);
    t[3] = padd(v3, a7); t[7] = psub(v3, a7);
}

// ---- apply geometric twiddle chain: t[q] *= w^q, q=1..7 --------------------------------------
__device__ __forceinline__ void twiddle_chain(float2* t, float2 w) {
    float2 wq = w;
    t[1] = cmulf2(t[1], wq);
#pragma unroll
    for (int q = 2; q < 8; q++) {
        wq = cmulf2(wq, w);
        t[q] = cmulf2(t[q], wq);
    }
}

// ---- 8x8 half2 transpose across 8 lanes (SHFL.32, 3 rounds) ---------------------------------
__device__ __forceinline__ void transpose8h(unsigned int* u, int jj) {
#pragma unroll
    for (int k = 0; k < 3; k++) {
        const int m = 1 << k;
        bool hi = (jj & m) != 0;
#pragma unroll
        for (int i0 = 0; i0 < 8; i0++) {
            if ((i0 & m) == 0) {
                int i1 = i0 | m;
                unsigned int snd = hi ? u[i0] : u[i1];
                unsigned int rcv = __shfl_xor_sync(0xffffffffu, snd, m);
                if (hi) u[i0] = rcv; else u[i1] = rcv;
            }
        }
    }
}

// ---------------- kernel 0: init (twiddles, hann pairs, zero accumulators) -------------------
__global__ void k_init() {
    int p = blockIdx.x * blockDim.x + threadIdx.x;   // 0..262143
    if (p < 256 * 512) {
        int rp = p >> 9, j = p & 511;
        const float STEP = 512.0f / 511.0f;
        float lc = fmaf((float)j, STEP, -256.0f);
        float h0, h1;
        {
            float lr = fmaf((float)(2 * rp), STEP, -256.0f);
            float rd = sqrtf(lc * lc + lr * lr);
            h0 = (rd > 256.0f) ? 0.0f : 0.5f * (1.0f + cospif(rd * (1.0f / 256.0f)));
        }
        {
            float lr = fmaf((float)(2 * rp + 1), STEP, -256.0f);
            float rd = sqrtf(lc * lc + lr * lr);
            h1 = (rd > 256.0f) ? 0.0f : 0.5f * (1.0f + cospif(rd * (1.0f / 256.0f)));
        }
        g_hann2[p] = __floats2half2_rn(h0, h1);
    }
    if (p < NFREQ * N) g_accum[p] = 0.f;
    if (p < N) {
        double ang = -6.283185307179586476925286766559 * (double)p / 512.0;
        g_tw[p] = make_float2((float)cos(ang), (float)sin(ang));
    }
    if (p < 32 * NFREQ) { ((float*)g_psum)[p] = 0.f; ((float*)g_pcnt)[p] = 0.f; }
    if (p == 0) g_done = 0u;
}

// ---------------- kernel 1: DIF row FFTs, GIMG images per block (window blocks: 1) ------------
__global__ void __launch_bounds__(256) k_rowfft(const float* __restrict__ src) {
    __shared__ __half2 smA[4][576];
    __shared__ __half2 smB[4][576];
    __shared__ float red[8];
    bool win = blockIdx.x >= 2048;
    int rgrp = win ? (int)blockIdx.x - 2048 : (int)blockIdx.x & 63;
    int igrp = win ? 0 : (int)blockIdx.x >> 6;
    int r0   = rgrp << 3;
    __half2* dst = win ? g_hrow : g_scratch;
    int kstride  = win ? N : RS;
    int niter    = win ? 1 : GIMG;

    int tid = threadIdx.x;
    int f   = tid >> 6, tau = tid & 63;
    int g   = tau >> 3, jj = tau & 7;
    int rowA = r0 + 2 * f;
    const __half2* hP = g_hann2 + ((rowA >> 1) << 9);
    __half2* sA = smA[f];
    __half2* sB = smB[f];
    float2 w0 = g_tw[tau];
    float2 w1 = g_tw[jj << 3];
    int pbS = tau + (tau >> 3);
    int pbL = 72 * g + jj;

    __half2 hreg[8];
#pragma unroll
    for (int m = 0; m < 8; m++) hreg[m] = hP[tau + (m << 6)];

    for (int it = 0; it < niter; it++) {
        int b = (igrp << 2) + it;
        size_t srcbase = ((size_t)b << 18) + ((size_t)rowA << 9);

        // ---- load + stage 0 (stride 64) in registers ----
        float2 t[8];
        float lsum = 0.f;
#pragma unroll
        for (int m = 0; m < 8; m++) {
            int c = tau + (m << 6);
            float2 h2 = __half22float2(hreg[m]);
            float va = 1.0f, vb = 1.0f;
            if (!win) {
                va = src[srcbase + c];
                vb = src[srcbase + 512 + c];
                lsum += va + vb;
            }
            t[m] = make_float2(va * h2.x, vb * h2.y);
        }
        dft8(t);
        twiddle_chain(t, w0);
#pragma unroll
        for (int q = 0; q < 8; q++) sA[pbS + 72 * q] = __floats2half2_rn(t[q].x, t[q].y);

#pragma unroll
        for (int o = 16; o; o >>= 1) lsum += __shfl_down_sync(0xffffffffu, lsum, o);
        __syncthreads();                        // sync1: smA ready; prev red consumed
        if ((tid & 31) == 0) red[tid >> 5] = lsum;

        // ---- stage 1 (stride 8) in registers ----
        float2 u[8];
#pragma unroll
        for (int m = 0; m < 8; m++) u[m] = __half22float2(sA[pbL + 9 * m]);
        dft8(u);
        twiddle_chain(u, w1);

        // ---- fp16 shuffle exchange + stage 2 ----
        unsigned int uh[8];
#pragma unroll
        for (int q = 0; q < 8; q++) { HU h; h.h = __floats2half2_rn(u[q].x, u[q].y); uh[q] = h.u; }
        transpose8h(uh, jj);
#pragma unroll
        for (int m = 0; m < 8; m++) { HU h; h.u = uh[m]; u[m] = __half22float2(h.h); }
        dft8(u);

#pragma unroll
        for (int m = 0; m < 8; m++)
            sB[adr2((m << 6) + (jj << 3) + g)] = __floats2half2_rn(u[m].x, u[m].y);
        __syncthreads();                        // sync2: smB + red ready

        if (tid == 0) {
            float tot = 0.f;
#pragma unroll
            for (int p = 0; p < 8; p++) tot += red[p];
            if (win) g_hparts[rgrp] = tot;
            else     g_parts[(b << 6) + rgrp] = tot;
        }

        // ---- Hermitian unpack: one thread per (pair,k) writes both rows as one STG.64 ----
        int p      = tid & 3;
        int kslot  = tid >> 2;
        __half2* so = smB[p];
        size_t dbase = ((size_t)b << 9) + r0 + 2 * p;
        if (win) dbase = r0 + 2 * p;
#pragma unroll
        for (int kk = 0; kk < 5; kk++) {
            int k = kslot + (kk << 6);
            if (k < NFREQ) {
                float2 z = __half22float2(so[adr2(k)]);
                float2 y = __half22float2(so[adr2((512 - k) & 511)]);
                __half2 A = __floats2half2_rn(0.5f * (z.x + y.x), 0.5f * (z.y - y.y));
                __half2 B = __floats2half2_rn(0.5f * (z.y + y.y), 0.5f * (y.x - z.x));
                F2U pack; ((__half2*)&pack.u)[0] = A; ((__half2*)&pack.u)[1] = B;
                *reinterpret_cast<unsigned long long*>(
                    &dst[(size_t)k * kstride + dbase]) = pack.u;
            }
        }
    }
}

// ---------------- kernel 2: DIF column FFTs — coalesced [c][r] reduction ----------------------
__global__ void __launch_bounds__(256, 4) k_colfft() {
    __shared__ __half2 smbuf[2][4][576];
    __shared__ float smean[8];
    int ct  = blockIdx.x % 65;
    int grp = blockIdx.x / 65;             // 0..15 : 8 images each
    int f   = threadIdx.x >> 6;
    int tau = threadIdx.x & 63;
    int g   = tau >> 3, jj = tau & 7;
    int c   = (ct << 2) + f;
    bool valid = (c < NFREQ);
    size_t cbase = valid ? (size_t)c * RS : 0;
    int b0 = grp << 3;
    int bar = f + 1;
    float2 w0 = g_tw[tau];
    float2 w1 = g_tw[jj << 3];

    __half2 hvh[8];
    size_t hbase = valid ? ((size_t)c << 9) : 0;
#pragma unroll
    for (int m = 0; m < 8; m++)
        hvh[m] = valid ? g_hrow[hbase + tau + (m << 6)] : __float2half2_rn(0.f);

    __half2 traw[8];
#pragma unroll
    for (int m = 0; m < 8; m++)
        traw[m] = valid ? g_scratch[cbase + ((size_t)b0 << 9) + tau + (m << 6)]
                        : __float2half2_rn(0.f);

    {
        int w = threadIdx.x >> 5, l = threadIdx.x & 31;
        float v = g_parts[((b0 + w) << 6) + l] + g_parts[((b0 + w) << 6) + 32 + l];
#pragma unroll
        for (int o = 16; o; o >>= 1) v += __shfl_down_sync(0xffffffffu, v, o);
        if (l == 0) smean[w] = v * (1.0f / 262144.0f);
        __syncthreads();
    }

    int pbS = tau + (tau >> 3);
    int pbL = 72 * g + jj;

    float acc[8];
#pragma unroll
    for (int m = 0; m < 8; m++) acc[m] = 0.f;

    for (int bi = 0; bi < 8; bi++) {
        __half2 mh = __float2half2_rn(-smean[bi]);
        __half2* s = smbuf[bi & 1][f];

        float2 tc[8];
#pragma unroll
        for (int m = 0; m < 8; m++) {
            __half2 th = __hfma2(mh, hvh[m], traw[m]);
            tc[m] = __half22float2(th);
        }
        dft8(tc);
        twiddle_chain(tc, w0);
#pragma unroll
        for (int q = 0; q < 8; q++)
            s[pbS + 72 * q] = __floats2half2_rn(tc[q].x, tc[q].y);

        if (bi < 7 && valid) {
            int b = b0 + bi + 1;
#pragma unroll
            for (int m = 0; m < 8; m++)
                traw[m] = g_scratch[cbase + ((size_t)b << 9) + tau + (m << 6)];
        }
        BARSYNC(bar);

        float2 u[8];
#pragma unroll
        for (int m = 0; m < 8; m++) u[m] = __half22float2(s[pbL + 9 * m]);
        dft8(u);
        twiddle_chain(u, w1);

        unsigned int uh[8];
#pragma unroll
        for (int q = 0; q < 8; q++) { HU h; h.h = __floats2half2_rn(u[q].x, u[q].y); uh[q] = h.u; }
        transpose8h(uh, jj);
#pragma unroll
        for (int m = 0; m < 8; m++) { HU h; h.u = uh[m]; u[m] = __half22float2(h.h); }
        dft8(u);
#pragma unroll
        for (int m = 0; m < 8; m++)
            acc[m] = fmaf(u[m].x, u[m].x, fmaf(u[m].y, u[m].y, acc[m]));
    }

    if (valid) {
        int rlo = (jj << 3) + g;
#pragma unroll
        for (int m = 0; m < 8; m++) {
            int r = (m << 6) + rlo;
            atomicAdd(&g_accum[c * N + r], acc[m]);   // [c][r]: warp lands in 2 lines
        }
    }
}

// ---------------- kernel 3: nps2D + radial binning (per-warp bins) + fused 1D tail ------------
// block = output COLUMN j; thread = output row i (2 rows each); 8 private bin copies.
__global__ void __launch_bounds__(256) k_finalize2d(float* __restrict__ out) {
    __shared__ float ssum[8][264];
    __shared__ float scnt[8][264];
    int j = blockIdx.x;
    int tid = threadIdx.x;
    int w = tid >> 5;
#pragma unroll
    for (int z = tid; z < 8 * 264; z += 256) {
        ((float*)ssum)[z] = 0.f;
        ((float*)scnt)[z] = 0.f;
    }
    __syncthreads();

    const float SC = (float)(0.01 / (262144.0 * 128.0));
    int v = j ^ 256;
    bool mir = v > 256;
    if (mir) v = 512 - v;
    const float* arow = g_accum + (size_t)v * N;   // coalesced row
    int yj = j - 256;
    int yj2 = yj * yj;

    float vals[2];
#pragma unroll
    for (int h = 0; h < 2; h++) {
        int i = tid + (h << 8);
        int u = i ^ 256;
        if (mir) u = (512 - u) & 511;
        vals[h] = arow[u] * SC;
    }
#pragma unroll
    for (int h = 0; h < 2; h++) {
        int i = tid + (h << 8);
        out[NFREQ + (i << 9) + j] = vals[h];       // scattered store: fire-and-forget
        int xi = i - 256;
        int rad = __float2int_rn(__fsqrt_rn((float)(xi * xi + yj2)));
        if (rad < NFREQ) {
            atomicAdd(&ssum[w][rad], vals[h]);     // per-warp bins: no inter-warp serialization
            atomicAdd(&scnt[w][rad], 1.0f);
        }
    }
    __syncthreads();

    // combine 8 warp copies, then one global partial-atomic per bin
    int part = j & 31;
#pragma unroll
    for (int h = 0; h < 2; h++) {
        int k = tid + (h << 8);
        if (k < NFREQ) {
            float s = 0.f, cth = 0.f;
#pragma unroll
            for (int p = 0; p < 8; p++) { s += ssum[p][k]; cth += scnt[p][k]; }
            if (s != 0.f || cth != 0.f) {
                atomicAdd(&g_psum[part][k], s);
                atomicAdd(&g_pcnt[part][k], cth);
            }
        }
    }

    // ---- fused 1D tail: last block to finish sums the partials ----
    __threadfence();
    __shared__ unsigned slast;
    __syncthreads();
    if (tid == 0) slast = atomicAdd(&g_done, 1u);
    __syncthreads();
    if (slast == (unsigned)(gridDim.x - 1)) {
        __threadfence();          // acquire: see all blocks' psum/pcnt
#pragma unroll
        for (int h = 0; h < 2; h++) {
            int k = tid + (h << 8);
            if (k < NFREQ) {
                float s = 0.f, cth = 0.f;
#pragma unroll
                for (int p = 0; p < 32; p++) { s += g_psum[p][k]; cth += g_pcnt[p][k]; }
                out[k] = s / cth;
                out[NFREQ + N * N + k] = 5.0f * (float)k / 256.0f;
            }
        }
    }
}

extern "C" void kernel_launch(void* const* d_in, const int* in_sizes, int n_in,
                              void* d_out, int out_size) {
    const float* x = (const float*)d_in[0];
    float* out = (float*)d_out;

    k_init<<<1024, 256>>>();
    k_rowfft<<<2048 + 64, 256>>>(x);           // 4 images/block + 64 window blocks
    k_colfft<<<65 * 16, 256>>>();              // 4 cols x 8 images per block
    k_finalize2d<<<N, 256>>>(out);             // column-blocks, per-warp bins, fused 1D tail
}